// round 10
// baseline (speedup 1.0000x reference)
#include <cuda_runtime.h>
#include <cuda_fp16.h>
#include <cstdint>

// Problem constants
#define BATCH 8
#define SEQ   4096
#define DM    1024
#define NH    16
#define NG    4
#define HD    64
#define HG    (NH*NG)          // 64
#define MROWS (BATCH*SEQ)      // 32768
#define INV_SCALE 0.125f       // 1/sqrt(64)
#define WSCALE 1024.0f
#define WUNSCALE (1.0f/1024.0f)

// ---------------------------------------------------------------------------
// Scratch (device globals)
// ---------------------------------------------------------------------------
__device__ float g_s1[MROWS * HG];              // exp(q-scores)
__device__ float g_s2[MROWS * HG];              // ksc; WqWqa fp32 tmp during prep
__device__ float g_b1[HG];                      // bq@Wqa + bqa
__device__ float g_zero[HG];
__device__ __align__(256) __half2 g_gmm1[BATCH * NH * HD];  // (gmax,gmin) of gq/cs
__device__ __align__(256) __half2 g_gmm2[BATCH * NH * HD];  // (gmax,gmin) of gk
__device__ __align__(256) __half g_qh[MROWS * DM];
__device__ __align__(256) __half g_kh[MROWS * DM];
__device__ __align__(256) __half g_vh[MROWS * DM];
__device__ __align__(256) __half g_ah[MROWS * DM];            // hs fp16
__device__ __align__(256) __half g_wcat[(3 * DM + 128) * DM]; // WqT|WkT|WvT|ws1pad
__device__ __align__(256) __half g_wt[DM * DM];               // WtT
__device__ __align__(256) __half g_ws2[HG * DM];              // WkaT

// ---------------------------------------------------------------------------
// PTX helpers (plain sm_103-safe)
// ---------------------------------------------------------------------------
__device__ __forceinline__ uint32_t smem_u32(const void* p) {
    uint32_t a;
    asm("{ .reg .u64 t; cvta.to.shared.u64 t, %1; cvt.u32.u64 %0, t; }"
        : "=r"(a) : "l"(p));
    return a;
}
#define CP_ASYNC16(s, g) \
    asm volatile("cp.async.cg.shared.global [%0], [%1], 16;" :: "r"(s), "l"(g))
#define CP_COMMIT() asm volatile("cp.async.commit_group;" ::: "memory")
#define CP_WAIT(n)  asm volatile("cp.async.wait_group %0;" :: "n"(n) : "memory")
#define LDMX4(r, addr) \
    asm volatile("ldmatrix.sync.aligned.m8n8.x4.shared.b16 {%0,%1,%2,%3}, [%4];" \
        : "=r"((r)[0]), "=r"((r)[1]), "=r"((r)[2]), "=r"((r)[3]) : "r"(addr))
#define MMA_F16(d, a, b0, b1) \
    asm volatile("mma.sync.aligned.m16n8k16.row.col.f32.f16.f16.f32 " \
        "{%0,%1,%2,%3}, {%4,%5,%6,%7}, {%8,%9}, {%0,%1,%2,%3};" \
        : "+f"((d)[0]), "+f"((d)[1]), "+f"((d)[2]), "+f"((d)[3]) \
        : "r"((a)[0]), "r"((a)[1]), "r"((a)[2]), "r"((a)[3]), "r"(b0), "r"(b1))

#define SWZ(o) ((uint32_t)(o) ^ ((((uint32_t)(o)) >> 3) & 0x70))

#define BK 64
#define STG_BIG 32768
#define SMEM_BIG (2 * STG_BIG)

// Apply max-trick to one uint4 (8 fp16) with 8 gmm half2 entries (m0,m1).
__device__ __forceinline__ uint4 maxg_apply(uint4 xv, uint4 m0, uint4 m1) {
    uint32_t out[4];
    const uint32_t* xw  = (const uint32_t*)&xv;
    const uint32_t* mw0 = (const uint32_t*)&m0;
    const uint32_t* mw1 = (const uint32_t*)&m1;
    #pragma unroll
    for (int j = 0; j < 4; ++j) {
        const uint32_t ga = (j < 2) ? mw0[2 * j]     : mw1[2 * j - 4];
        const uint32_t gb = (j < 2) ? mw0[2 * j + 1] : mw1[2 * j - 3];
        const __half2 x2 = *(const __half2*)&xw[j];
        const __half2 g0 = *(const __half2*)&ga;   // (gmax_d, gmin_d)
        const __half2 g1 = *(const __half2*)&gb;
        const float x0 = __low2float(x2), x1 = __high2float(x2);
        const float s0 = (x0 >= 0.f) ? __low2float(g0) : __high2float(g0);
        const float s1 = (x1 >= 0.f) ? __low2float(g1) : __high2float(g1);
        const __half2 r = __floats2half2_rn(x0 * s0, x1 * s1);
        out[j] = *(const uint32_t*)&r;
    }
    return *(const uint4*)out;
}

// ---------------------------------------------------------------------------
// Fused QKV+S1 GEMM (unchanged).
// ---------------------------------------------------------------------------
__global__ __launch_bounds__(256, 2) void gemm_qkvs(
    const __half* __restrict__ A, const __half* __restrict__ B,
    const float* __restrict__ bq, const float* __restrict__ bk,
    const float* __restrict__ bv, const float* __restrict__ b1,
    const float* __restrict__ mask,
    __half* __restrict__ Q, __half* __restrict__ K, __half* __restrict__ V,
    float* __restrict__ S1)
{
    extern __shared__ char smem[];
    const uint32_t sbase = smem_u32(smem);
    const int tid  = threadIdx.x;
    const int lane = tid & 31;
    const int wid  = tid >> 5;
    const int wm   = wid & 3;
    const int wn   = wid >> 2;
    const int brow = blockIdx.y * 128;
    const int bcol = blockIdx.x * 128;
    const int which = blockIdx.x >> 3;
    const int bcl   = bcol & (DM - 1);
    const float* bias = which == 0 ? bq : which == 1 ? bk : which == 2 ? bv : b1;

    const int lrow  = tid >> 1;
    const int lhalf = tid & 1;
    const __half* gA = A + (size_t)(brow + lrow) * DM + lhalf * 32;
    const __half* gB = B + (size_t)(bcol + lrow) * DM + lhalf * 32;
    uint32_t soff[4];
    #pragma unroll
    for (int i = 0; i < 4; ++i)
        soff[i] = SWZ(lrow * 128 + lhalf * 64 + i * 16);

    float acc[2][8][4];
    #pragma unroll
    for (int mi = 0; mi < 2; ++mi)
        #pragma unroll
        for (int nt = 0; nt < 8; ++nt)
            #pragma unroll
            for (int r = 0; r < 4; ++r) acc[mi][nt][r] = 0.f;

    const int frow = lane & 15;
    const int fcol = (lane >> 4) << 4;

    {
        #pragma unroll
        for (int i = 0; i < 4; ++i) {
            CP_ASYNC16(sbase +         soff[i], gA + i * 8);
            CP_ASYNC16(sbase + 16384 + soff[i], gB + i * 8);
        }
        CP_COMMIT();
    }

    #pragma unroll 1
    for (int c = 0; c < 16; ++c) {
        const int s = c & 1;
        if (c + 1 < 16) {
            const uint32_t sb = sbase + ((c + 1) & 1) * STG_BIG;
            const size_t ko = (size_t)(c + 1) * BK;
            #pragma unroll
            for (int i = 0; i < 4; ++i) {
                CP_ASYNC16(sb +         soff[i], gA + ko + i * 8);
                CP_ASYNC16(sb + 16384 + soff[i], gB + ko + i * 8);
            }
            CP_COMMIT();
            CP_WAIT(1);
        } else {
            CP_WAIT(0);
        }
        __syncthreads();

        const uint32_t stg = sbase + s * STG_BIG;
        #pragma unroll
        for (int ks = 0; ks < 4; ++ks) {
            const uint32_t kb = ks * 32 + fcol;
            uint32_t a_r[2][4];
            #pragma unroll
            for (int mi = 0; mi < 2; ++mi) {
                const uint32_t o = SWZ((wm * 32 + mi * 16 + frow) * 128 + kb);
                LDMX4(a_r[mi], stg + o);
            }
            uint32_t b_r[4][4];
            #pragma unroll
            for (int nt2 = 0; nt2 < 4; ++nt2) {
                const uint32_t o = SWZ((wn * 64 + nt2 * 16 + frow) * 128 + kb);
                LDMX4(b_r[nt2], stg + 16384 + o);
            }
            #pragma unroll
            for (int mi = 0; mi < 2; ++mi)
                #pragma unroll
                for (int nt = 0; nt < 8; ++nt)
                    MMA_F16(acc[mi][nt], a_r[mi], b_r[nt >> 1][nt & 1], b_r[nt >> 1][(nt & 1) + 2]);
        }
        __syncthreads();
    }

    const int er = brow + wm * 32 + (lane >> 2);
    const int ec = bcl + wn * 64 + (lane & 3) * 2;
    if (which < 3) {
        __half* Ch = which == 0 ? Q : which == 1 ? K : V;
        #pragma unroll
        for (int mi = 0; mi < 2; ++mi) {
            #pragma unroll
            for (int nt = 0; nt < 8; ++nt) {
                const int row = er + mi * 16;
                const int col = ec + nt * 8;
                const float b0 = bias[col], b1v = bias[col + 1];
                *(__half2*)(Ch + (size_t)row * DM + col) =
                    __floats2half2_rn(acc[mi][nt][0] * WUNSCALE + b0,
                                      acc[mi][nt][1] * WUNSCALE + b1v);
                *(__half2*)(Ch + (size_t)(row + 8) * DM + col) =
                    __floats2half2_rn(acc[mi][nt][2] * WUNSCALE + b0,
                                      acc[mi][nt][3] * WUNSCALE + b1v);
            }
        }
    } else if (wn == 0) {
        #pragma unroll
        for (int mi = 0; mi < 2; ++mi) {
            #pragma unroll
            for (int nt = 0; nt < 8; ++nt) {
                const int row = er + mi * 16;
                const int col = (nt * 8 + (lane & 3) * 2);
                const float b0 = bias[col], b1v = bias[col + 1];
                const float m0 = mask[row], m1 = mask[row + 8];
                S1[(size_t)row * HG + col] =
                    __expf((acc[mi][nt][0] * WUNSCALE + b0) * INV_SCALE + m0);
                S1[(size_t)row * HG + col + 1] =
                    __expf((acc[mi][nt][1] * WUNSCALE + b1v) * INV_SCALE + m0);
                S1[(size_t)(row + 8) * HG + col] =
                    __expf((acc[mi][nt][2] * WUNSCALE + b0) * INV_SCALE + m1);
                S1[(size_t)(row + 8) * HG + col + 1] =
                    __expf((acc[mi][nt][3] * WUNSCALE + b1v) * INV_SCALE + m1);
            }
        }
    }
}

// ---------------------------------------------------------------------------
// Final GEMM, fused u: X staged via cp.async, converted IN PLACE (async X).
// out = (vh*sel(gmm2)) @ WtT + bt + qh
// ---------------------------------------------------------------------------
#define GMM_OFF (2 * STG_BIG)
#define SMEM_BIGF (2 * STG_BIG + 4096)

__global__ __launch_bounds__(256, 2) void gemm_hmma_f(
    const __half* __restrict__ X, const __half2* __restrict__ gmm,
    const __half* __restrict__ B,
    const float* __restrict__ bias, const __half* __restrict__ addv,
    float* __restrict__ C)
{
    extern __shared__ char smem[];
    const uint32_t sbase = smem_u32(smem);
    const int tid  = threadIdx.x;
    const int lane = tid & 31;
    const int wid  = tid >> 5;
    const int wm   = wid & 3;
    const int wn   = wid >> 2;
    const int brow = blockIdx.y * 128;
    const int bcol = blockIdx.x * 128;
    const int bb   = brow >> 12;

    const int lrow  = tid >> 1;
    const int lhalf = tid & 1;
    const __half* gX = X + (size_t)(brow + lrow) * DM + lhalf * 32;
    const __half* gB = B + (size_t)(bcol + lrow) * DM + lhalf * 32;
    uint32_t soff[4];
    #pragma unroll
    for (int i = 0; i < 4; ++i)
        soff[i] = SWZ(lrow * 128 + lhalf * 64 + i * 16);

    // one-time gmm slice load: 4KB
    *(uint4*)(smem + GMM_OFF + tid * 16) =
        ((const uint4*)(gmm + (size_t)bb * NH * HD))[tid];

    // prologue: X + B chunk 0 (both async)
    {
        #pragma unroll
        for (int i = 0; i < 4; ++i) {
            CP_ASYNC16(sbase +         soff[i], gX + i * 8);
            CP_ASYNC16(sbase + 16384 + soff[i], gB + i * 8);
        }
        CP_COMMIT();
    }
    __syncthreads();   // gmm visible

    float acc[2][8][4];
    #pragma unroll
    for (int mi = 0; mi < 2; ++mi)
        #pragma unroll
        for (int nt = 0; nt < 8; ++nt)
            #pragma unroll
            for (int r = 0; r < 4; ++r) acc[mi][nt][r] = 0.f;

    const int frow = lane & 15;
    const int fcol = (lane >> 4) << 4;
    const uint32_t gmo = GMM_OFF + lhalf * 128;

    #pragma unroll 1
    for (int c = 0; c < 16; ++c) {
        const int s = c & 1;
        if (c + 1 < 16) {
            const uint32_t sb = sbase + ((c + 1) & 1) * STG_BIG;
            const size_t ko = (size_t)(c + 1) * BK;
            #pragma unroll
            for (int i = 0; i < 4; ++i) {
                CP_ASYNC16(sb +         soff[i], gX + ko + i * 8);
                CP_ASYNC16(sb + 16384 + soff[i], gB + ko + i * 8);
            }
            CP_COMMIT();
            CP_WAIT(1);
        } else {
            CP_WAIT(0);
        }

        // in-place convert: own cp.async data is visible after wait
        {
            const uint32_t go = gmo + c * 256;
            char* sA = smem + s * STG_BIG;
            #pragma unroll
            for (int i = 0; i < 4; ++i) {
                const uint4 xv = *(const uint4*)(sA + soff[i]);
                const uint4 m0 = *(const uint4*)(smem + go + i * 32);
                const uint4 m1 = *(const uint4*)(smem + go + i * 32 + 16);
                *(uint4*)(sA + soff[i]) = maxg_apply(xv, m0, m1);
            }
        }
        __syncthreads();

        const uint32_t stg = sbase + s * STG_BIG;
        #pragma unroll
        for (int ks = 0; ks < 4; ++ks) {
            const uint32_t kb = ks * 32 + fcol;
            uint32_t a_r[2][4];
            #pragma unroll
            for (int mi = 0; mi < 2; ++mi) {
                const uint32_t o = SWZ((wm * 32 + mi * 16 + frow) * 128 + kb);
                LDMX4(a_r[mi], stg + o);
            }
            uint32_t b_r[4][4];
            #pragma unroll
            for (int nt2 = 0; nt2 < 4; ++nt2) {
                const uint32_t o = SWZ((wn * 64 + nt2 * 16 + frow) * 128 + kb);
                LDMX4(b_r[nt2], stg + 16384 + o);
            }
            #pragma unroll
            for (int mi = 0; mi < 2; ++mi)
                #pragma unroll
                for (int nt = 0; nt < 8; ++nt)
                    MMA_F16(acc[mi][nt], a_r[mi], b_r[nt >> 1][nt & 1], b_r[nt >> 1][(nt & 1) + 2]);
        }
        __syncthreads();
    }

    const int er = brow + wm * 32 + (lane >> 2);
    const int ec = bcol + wn * 64 + (lane & 3) * 2;
    #pragma unroll
    for (int mi = 0; mi < 2; ++mi) {
        #pragma unroll
        for (int nt = 0; nt < 8; ++nt) {
            const int row = er + mi * 16;
            const int col = ec + nt * 8;
            const float b0 = bias[col], b1v = bias[col + 1];
            const float2 f0 = __half22float2(*(const __half2*)(addv + (size_t)row * DM + col));
            const float2 f1 = __half22float2(*(const __half2*)(addv + (size_t)(row + 8) * DM + col));
            *(float2*)(C + (size_t)row * DM + col) = make_float2(
                acc[mi][nt][0] * WUNSCALE + b0 + f0.x,
                acc[mi][nt][1] * WUNSCALE + b1v + f0.y);
            *(float2*)(C + (size_t)(row + 8) * DM + col) = make_float2(
                acc[mi][nt][2] * WUNSCALE + b0 + f1.x,
                acc[mi][nt][3] * WUNSCALE + b1v + f1.y);
        }
    }
}

// ---------------------------------------------------------------------------
// N=64 GEMM, fused qk: async X + in-place convert; ksc epilogue.
// ---------------------------------------------------------------------------
#define STG_N64 24576
#define GMM_OFF64 (2 * STG_N64)
#define SMEM_N64F (2 * STG_N64 + 4096)

__global__ __launch_bounds__(256, 2) void gemm_n64_f(
    const __half* __restrict__ X, const __half2* __restrict__ gmm,
    const __half* __restrict__ B,
    const float* __restrict__ bias, const float* __restrict__ mask,
    float* __restrict__ C)
{
    extern __shared__ char smem[];
    const uint32_t sbase = smem_u32(smem);
    const int tid  = threadIdx.x;
    const int lane = tid & 31;
    const int wid  = tid >> 5;
    const int wm   = wid & 3;
    const int wn   = wid >> 2;
    const int brow = blockIdx.x * 128;
    const int bb   = brow >> 12;

    const int lrow  = tid >> 1;
    const int lhalf = tid & 1;
    const __half* gX = X + (size_t)(brow + lrow) * DM + lhalf * 32;
    uint32_t aoff[4];
    #pragma unroll
    for (int i = 0; i < 4; ++i)
        aoff[i] = SWZ(lrow * 128 + lhalf * 64 + i * 16);
    const int  brw   = (tid & 127) >> 1;
    const int  bhalf = tid & 1;
    const bool bldr  = tid < 128;
    const __half* gB = B + (size_t)brw * DM + bhalf * 32;
    uint32_t boff[4];
    #pragma unroll
    for (int i = 0; i < 4; ++i)
        boff[i] = SWZ(brw * 128 + bhalf * 64 + i * 16);

    *(uint4*)(smem + GMM_OFF64 + tid * 16) =
        ((const uint4*)(gmm + (size_t)bb * NH * HD))[tid];

    {
        #pragma unroll
        for (int i = 0; i < 4; ++i) {
            CP_ASYNC16(sbase + aoff[i], gX + i * 8);
            if (bldr) CP_ASYNC16(sbase + 16384 + boff[i], gB + i * 8);
        }
        CP_COMMIT();
    }
    __syncthreads();

    float acc[2][4][4];
    #pragma unroll
    for (int mi = 0; mi < 2; ++mi)
        #pragma unroll
        for (int nt = 0; nt < 4; ++nt)
            #pragma unroll
            for (int r = 0; r < 4; ++r) acc[mi][nt][r] = 0.f;

    const int frow = lane & 15;
    const int fcol = (lane >> 4) << 4;
    const uint32_t gmo = GMM_OFF64 + lhalf * 128;

    #pragma unroll 1
    for (int c = 0; c < 16; ++c) {
        const int s = c & 1;
        if (c + 1 < 16) {
            const uint32_t sb = sbase + ((c + 1) & 1) * STG_N64;
            const size_t ko = (size_t)(c + 1) * BK;
            #pragma unroll
            for (int i = 0; i < 4; ++i) {
                CP_ASYNC16(sb + aoff[i], gX + ko + i * 8);
                if (bldr) CP_ASYNC16(sb + 16384 + boff[i], gB + ko + i * 8);
            }
            CP_COMMIT();
            CP_WAIT(1);
        } else {
            CP_WAIT(0);
        }

        {
            const uint32_t go = gmo + c * 256;
            char* sA = smem + s * STG_N64;
            #pragma unroll
            for (int i = 0; i < 4; ++i) {
                const uint4 xv = *(const uint4*)(sA + aoff[i]);
                const uint4 m0 = *(const uint4*)(smem + go + i * 32);
                const uint4 m1 = *(const uint4*)(smem + go + i * 32 + 16);
                *(uint4*)(sA + aoff[i]) = maxg_apply(xv, m0, m1);
            }
        }
        __syncthreads();

        const uint32_t stg = sbase + s * STG_N64;
        #pragma unroll
        for (int ks = 0; ks < 4; ++ks) {
            const uint32_t kb = ks * 32 + fcol;
            uint32_t a_r[2][4];
            #pragma unroll
            for (int mi = 0; mi < 2; ++mi) {
                const uint32_t o = SWZ((wm * 32 + mi * 16 + frow) * 128 + kb);
                LDMX4(a_r[mi], stg + o);
            }
            uint32_t b_r[2][4];
            #pragma unroll
            for (int nt2 = 0; nt2 < 2; ++nt2) {
                const uint32_t o = SWZ((wn * 32 + nt2 * 16 + frow) * 128 + kb);
                LDMX4(b_r[nt2], stg + 16384 + o);
            }
            #pragma unroll
            for (int mi = 0; mi < 2; ++mi)
                #pragma unroll
                for (int nt = 0; nt < 4; ++nt)
                    MMA_F16(acc[mi][nt], a_r[mi], b_r[nt >> 1][nt & 1], b_r[nt >> 1][(nt & 1) + 2]);
        }
        __syncthreads();
    }

    const int er = brow + wm * 32 + (lane >> 2);
    const int ec = wn * 32 + (lane & 3) * 2;
    #pragma unroll
    for (int mi = 0; mi < 2; ++mi) {
        #pragma unroll
        for (int nt = 0; nt < 4; ++nt) {
            const int row = er + mi * 16;
            const int col = ec + nt * 8;
            const float b0 = bias[col], b1v = bias[col + 1];
            const float m0 = mask[row], m1 = mask[row + 8];
            *(float2*)(C + (size_t)row * HG + col) = make_float2(
                (acc[mi][nt][0] * WUNSCALE + b0) * INV_SCALE + m0,
                (acc[mi][nt][1] * WUNSCALE + b1v) * INV_SCALE + m0);
            *(float2*)(C + (size_t)(row + 8) * HG + col) = make_float2(
                (acc[mi][nt][2] * WUNSCALE + b0) * INV_SCALE + m1,
                (acc[mi][nt][3] * WUNSCALE + b1v) * INV_SCALE + m1);
        }
    }
}

// ---------------------------------------------------------------------------
// Fused gsum + colsum + gminmax.  One CTA per (b,h), 512 threads, no atomics.
// tid = q(2b) | g(2b) | dp(5b): n-quarter, group, d-pair.
// gmm[b,h,d] = (max_g, min_g) of [sum_n w*x] (optionally / sum_n w).
// ---------------------------------------------------------------------------
__global__ __launch_bounds__(512, 2) void gsum_fused(
    const __half* __restrict__ x, const float* __restrict__ w,
    int normalize, __half2* __restrict__ gmm)
{
    const int bh = blockIdx.x;               // b*NH + h
    const int b = bh >> 4, h = bh & 15;
    const int qn = threadIdx.x >> 7;         // 0..3 (n-quarter)
    const int g  = (threadIdx.x >> 5) & 3;
    const int dp = threadIdx.x & 31;         // d-pair

    const __half2* xp = (const __half2*)(x
        + ((size_t)b * SEQ + qn * 1024) * DM + h * HD + dp * 2);
    const float* wp = w + ((size_t)b * SEQ + qn * 1024) * HG + h * NG + g;

    float ax0 = 0.f, ay0 = 0.f, ax1 = 0.f, ay1 = 0.f;
    float c0 = 0.f, c1 = 0.f;
    #pragma unroll 2
    for (int n = 0; n < 1024; n += 2) {
        const float w0 = wp[(size_t)(n + 0) * HG];
        const float w1 = wp[(size_t)(n + 1) * HG];
        const float2 v0 = __half22float2(xp[(size_t)(n + 0) * (DM / 2)]);
        const float2 v1 = __half22float2(xp[(size_t)(n + 1) * (DM / 2)]);
        ax0 = fmaf(v0.x, w0, ax0); ay0 = fmaf(v0.y, w0, ay0);
        ax1 = fmaf(v1.x, w1, ax1); ay1 = fmaf(v1.y, w1, ay1);
        c0 += w0; c1 += w1;
    }

    __shared__ float sg[4][4][64];   // [quarter][g][d]
    __shared__ float sc[4][4];       // [quarter][g]
    sg[qn][g][dp * 2]     = ax0 + ax1;
    sg[qn][g][dp * 2 + 1] = ay0 + ay1;
    if (dp == 0) sc[qn][g] = c0 + c1;
    __syncthreads();

    if (threadIdx.x < 256) {
        const int gg = threadIdx.x >> 6, dd = threadIdx.x & 63;
        float v = (sg[0][gg][dd] + sg[1][gg][dd])
                + (sg[2][gg][dd] + sg[3][gg][dd]);
        if (normalize) {
            const float cs = (sc[0][gg] + sc[1][gg]) + (sc[2][gg] + sc[3][gg]);
            v /= cs;
        }
        __syncthreads();
        sg[0][gg][dd] = v;
    } else {
        __syncthreads();
    }
    __syncthreads();

    if (threadIdx.x < 64) {
        const int dd = threadIdx.x;
        const float v0 = sg[0][0][dd], v1 = sg[0][1][dd];
        const float v2 = sg[0][2][dd], v3 = sg[0][3][dd];
        gmm[(size_t)bh * HD + dd] = __floats2half2_rn(
            fmaxf(fmaxf(v0, v1), fmaxf(v2, v3)),
            fminf(fminf(v0, v1), fminf(v2, v3)));
    }
}

// ---------------------------------------------------------------------------
// prep kernels
// ---------------------------------------------------------------------------
__global__ __launch_bounds__(256) void tofp16(
    const float4* __restrict__ x, __half2* __restrict__ o)
{
    const size_t i = (size_t)blockIdx.x * 256 + threadIdx.x;
    const float4 v = x[i];
    o[2 * i]     = __floats2half2_rn(v.x, v.y);
    o[2 * i + 1] = __floats2half2_rn(v.z, v.w);
}

__global__ __launch_bounds__(256) void wconv4(
    const float* __restrict__ W0, const float* __restrict__ W1,
    const float* __restrict__ W2, const float* __restrict__ W3,
    __half* __restrict__ Tcat, __half* __restrict__ Twt)
{
    __shared__ float tile[32][33];
    const int z = blockIdx.z;
    const float* W = z == 0 ? W0 : z == 1 ? W1 : z == 2 ? W2 : W3;
    __half* Tz = z < 3 ? Tcat + (size_t)z * DM * DM : Twt;
    const int bn = blockIdx.x * 32;
    const int bk = blockIdx.y * 32;
    const int x = threadIdx.x;
    const int y = threadIdx.y;
    #pragma unroll
    for (int i = 0; i < 32; i += 8)
        tile[y + i][x] = W[(size_t)(bk + y + i) * DM + bn + x];
    __syncthreads();
    #pragma unroll
    for (int i = 0; i < 32; i += 8)
        Tz[(size_t)(bn + y + i) * DM + bk + x] =
            __float2half_rn(tile[x][y + i] * WSCALE);
}

__global__ __launch_bounds__(256) void wconv_t(
    const float* __restrict__ W, __half* __restrict__ T, int ncols)
{
    __shared__ float tile[32][33];
    const int bn = blockIdx.x * 32;
    const int bk = blockIdx.y * 32;
    const int x = threadIdx.x;
    const int y = threadIdx.y;
    #pragma unroll
    for (int i = 0; i < 32; i += 8)
        tile[y + i][x] = W[(size_t)(bk + y + i) * ncols + bn + x];
    __syncthreads();
    #pragma unroll
    for (int i = 0; i < 32; i += 8)
        T[(size_t)(bn + y + i) * DM + bk + x] =
            __float2half_rn(tile[x][y + i] * WSCALE);
}

__global__ __launch_bounds__(256) void sgemm_small(
    const float* __restrict__ A, const float* __restrict__ W,
    const float* __restrict__ bias, float* __restrict__ C)
{
    __shared__ __align__(16) float As[16][64];
    __shared__ __align__(16) float Bs[16][64];
    const int tid  = threadIdx.x;
    const int brow = blockIdx.y * 64;
    const int arow = tid >> 2;
    const int akof = (tid & 3) * 4;
    const int bkr  = tid >> 4;
    const int bc4  = (tid & 15) * 4;
    const int trow = (tid >> 4) * 4;
    const int tcol = (tid & 15) * 4;

    float acc[4][4];
    #pragma unroll
    for (int i = 0; i < 4; i++)
        #pragma unroll
        for (int j = 0; j < 4; j++) acc[i][j] = 0.f;

    const float* Ab = A + (size_t)(brow + arow) * DM + akof;
    const float* Wb = W + (size_t)bkr * HG + bc4;

    for (int k0 = 0; k0 < DM; k0 += 16) {
        float4 av = *(const float4*)(Ab + k0);
        As[akof + 0][arow] = av.x;
        As[akof + 1][arow] = av.y;
        As[akof + 2][arow] = av.z;
        As[akof + 3][arow] = av.w;
        float4 bv = *(const float4*)(Wb + (size_t)k0 * HG);
        *(float4*)&Bs[bkr][bc4] = bv;
        __syncthreads();
        #pragma unroll
        for (int kk = 0; kk < 16; kk++) {
            float4 a0 = *(const float4*)&As[kk][trow];
            float4 b0 = *(const float4*)&Bs[kk][tcol];
            float ar[4] = {a0.x, a0.y, a0.z, a0.w};
            float br[4] = {b0.x, b0.y, b0.z, b0.w};
            #pragma unroll
            for (int i = 0; i < 4; i++)
                #pragma unroll
                for (int j = 0; j < 4; j++)
                    acc[i][j] = fmaf(ar[i], br[j], acc[i][j]);
        }
        __syncthreads();
    }
    #pragma unroll
    for (int i = 0; i < 4; i++)
        #pragma unroll
        for (int j = 0; j < 4; j++)
            C[(size_t)(brow + trow + i) * HG + tcol + j] = acc[i][j] + bias[tcol + j];
}

__global__ void bias_comb(const float* __restrict__ bq,
                          const float* __restrict__ Wqa,
                          const float* __restrict__ bqa,
                          float* __restrict__ b1)
{
    __shared__ float part[4][HG];
    const int j = threadIdx.x & 63;
    const int p = threadIdx.x >> 6;
    float s = 0.f;
    for (int i = p * 256; i < (p + 1) * 256; ++i)
        s = fmaf(bq[i], Wqa[(size_t)i * HG + j], s);
    part[p][j] = s;
    __syncthreads();
    if (p == 0)
        b1[j] = bqa[j] + ((part[0][j] + part[1][j]) + (part[2][j] + part[3][j]));
}

// zero the ws1 pad rows (64..127 of the 4th wcat section): 64*1024 halves
__global__ __launch_bounds__(256) void zero_pad(uint4* __restrict__ pad)
{
    pad[blockIdx.x * 256 + threadIdx.x] = make_uint4(0, 0, 0, 0);
}

// ---------------------------------------------------------------------------
// Launch
// ---------------------------------------------------------------------------
extern "C" void kernel_launch(void* const* d_in, const int* in_sizes, int n_in,
                              void* d_out, int out_size)
{
    const float* hs   = (const float*)d_in[0];
    const float* mask = (const float*)d_in[1];
    const float* Wq   = (const float*)d_in[2];
    const float* bq   = (const float*)d_in[3];
    const float* Wqa  = (const float*)d_in[4];
    const float* bqa  = (const float*)d_in[5];
    const float* Wk   = (const float*)d_in[6];
    const float* bk   = (const float*)d_in[7];
    const float* Wka  = (const float*)d_in[8];
    const float* bka  = (const float*)d_in[9];
    const float* Wv   = (const float*)d_in[10];
    const float* bv   = (const float*)d_in[11];
    const float* Wt   = (const float*)d_in[12];
    const float* bt   = (const float*)d_in[13];
    float* out = (float*)d_out;

    float *s1, *s2, *b1, *zv;
    __half2 *gmm1, *gmm2;
    __half *qh, *kh, *vh, *ah, *wcat, *wt, *ws2;
    cudaGetSymbolAddress((void**)&s1,   g_s1);
    cudaGetSymbolAddress((void**)&s2,   g_s2);
    cudaGetSymbolAddress((void**)&b1,   g_b1);
    cudaGetSymbolAddress((void**)&zv,   g_zero);
    cudaGetSymbolAddress((void**)&gmm1, g_gmm1);
    cudaGetSymbolAddress((void**)&gmm2, g_gmm2);
    cudaGetSymbolAddress((void**)&qh,   g_qh);
    cudaGetSymbolAddress((void**)&kh,   g_kh);
    cudaGetSymbolAddress((void**)&vh,   g_vh);
    cudaGetSymbolAddress((void**)&ah,   g_ah);
    cudaGetSymbolAddress((void**)&wcat, g_wcat);
    cudaGetSymbolAddress((void**)&wt,   g_wt);
    cudaGetSymbolAddress((void**)&ws2,  g_ws2);

    cudaFuncSetAttribute(gemm_qkvs,   cudaFuncAttributeMaxDynamicSharedMemorySize, SMEM_BIG);
    cudaFuncSetAttribute(gemm_hmma_f, cudaFuncAttributeMaxDynamicSharedMemorySize, SMEM_BIGF);
    cudaFuncSetAttribute(gemm_n64_f,  cudaFuncAttributeMaxDynamicSharedMemorySize, SMEM_N64F);

    const size_t WSZ = (size_t)DM * DM;
    __half* ws1 = wcat + 3 * WSZ;
    uint4* pad = (uint4*)(wcat + 3 * WSZ + 64 * DM);   // 64 rows x 1024 halves

    dim3 bW(32, 8);

    // --- prep ---
    zero_pad<<<(64 * DM / 8) / 256, 256>>>(pad);
    wconv4<<<dim3(DM / 32, DM / 32, 4), bW>>>(Wq, Wk, Wv, Wt, wcat, wt);
    sgemm_small<<<dim3(1, DM / 64), 256>>>(Wq, Wqa, zv, s2);
    wconv_t<<<dim3(HG / 32, DM / 32), bW>>>(s2, ws1, HG);
    bias_comb<<<1, 256>>>(bq, Wqa, bqa, b1);
    wconv_t<<<dim3(HG / 32, DM / 32), bW>>>(Wka, ws2, HG);
    tofp16<<<(MROWS * DM / 4) / 256, 256>>>((const float4*)hs, (__half2*)ah);

    // --- fused q,k,v,s1 projection ---
    gemm_qkvs<<<dim3(25, MROWS / 128), 256, SMEM_BIG>>>(
        ah, wcat, bq, bk, bv, b1, mask, qh, kh, vh, s1);

    // --- q-attention reduction (fused gsum+colsum+minmax) ---
    gsum_fused<<<BATCH * NH, 512>>>(qh, s1, 1, gmm1);

    // --- ksc (fused qk from kh+gmm1) -> k-side reduction ---
    gemm_n64_f<<<MROWS / 128, 256, SMEM_N64F>>>(kh, gmm1, ws2, bka, mask, s2);
    gsum_fused<<<BATCH * NH, 512>>>(kh, s2, 0, gmm2);

    // --- out = (fused u from vh+gmm2) @ Wt + bt + qh ---
    gemm_hmma_f<<<dim3(DM / 128, MROWS / 128), 256, SMEM_BIGF>>>(
        vh, gmm2, wt, bt, qh, out);
}

// round 11
// speedup vs baseline: 1.0002x; 1.0002x over previous
#include <cuda_runtime.h>
#include <cuda_fp16.h>
#include <cstdint>

// Problem constants
#define BATCH 8
#define SEQ   4096
#define DM    1024
#define NH    16
#define NG    4
#define HD    64
#define HG    (NH*NG)          // 64
#define MROWS (BATCH*SEQ)      // 32768
#define INV_SCALE 0.125f       // 1/sqrt(64)
#define WSCALE 1024.0f
#define WUNSCALE (1.0f/1024.0f)

// ---------------------------------------------------------------------------
// Scratch (device globals)
// ---------------------------------------------------------------------------
__device__ float g_s1[MROWS * HG];              // exp(q-scores)
__device__ float g_s2[MROWS * HG];              // ksc; WqWqa fp32 tmp during prep
__device__ float g_b1[HG];                      // bq@Wqa + bqa
__device__ float g_zero[HG];
__device__ __align__(256) __half2 g_gmm1[BATCH * NH * HD];  // (gmax,gmin) of gq/cs
__device__ __align__(256) __half2 g_gmm2[BATCH * NH * HD];  // (gmax,gmin) of gk
__device__ __align__(256) __half g_qh[MROWS * DM];
__device__ __align__(256) __half g_kh[MROWS * DM];
__device__ __align__(256) __half g_vh[MROWS * DM];
__device__ __align__(256) __half g_ah[MROWS * DM];            // hs fp16
__device__ __align__(256) __half g_wcat[(3 * DM + 128) * DM]; // WqT|WkT|WvT|ws1pad
__device__ __align__(256) __half g_wt[DM * DM];               // WtT
__device__ __align__(256) __half g_ws2[HG * DM];              // WkaT

// ---------------------------------------------------------------------------
// PTX helpers (plain sm_103-safe)
// ---------------------------------------------------------------------------
__device__ __forceinline__ uint32_t smem_u32(const void* p) {
    uint32_t a;
    asm("{ .reg .u64 t; cvta.to.shared.u64 t, %1; cvt.u32.u64 %0, t; }"
        : "=r"(a) : "l"(p));
    return a;
}
#define CP_ASYNC16(s, g) \
    asm volatile("cp.async.cg.shared.global [%0], [%1], 16;" :: "r"(s), "l"(g))
#define CP_COMMIT() asm volatile("cp.async.commit_group;" ::: "memory")
#define CP_WAIT(n)  asm volatile("cp.async.wait_group %0;" :: "n"(n) : "memory")
#define LDMX4(r, addr) \
    asm volatile("ldmatrix.sync.aligned.m8n8.x4.shared.b16 {%0,%1,%2,%3}, [%4];" \
        : "=r"((r)[0]), "=r"((r)[1]), "=r"((r)[2]), "=r"((r)[3]) : "r"(addr))
#define MMA_F16(d, a, b0, b1) \
    asm volatile("mma.sync.aligned.m16n8k16.row.col.f32.f16.f16.f32 " \
        "{%0,%1,%2,%3}, {%4,%5,%6,%7}, {%8,%9}, {%0,%1,%2,%3};" \
        : "+f"((d)[0]), "+f"((d)[1]), "+f"((d)[2]), "+f"((d)[3]) \
        : "r"((a)[0]), "r"((a)[1]), "r"((a)[2]), "r"((a)[3]), "r"(b0), "r"(b1))

#define SWZ(o) ((uint32_t)(o) ^ ((((uint32_t)(o)) >> 3) & 0x70))

#define BK 64
#define STG_BIG 32768
#define SMEM_BIG (2 * STG_BIG)

// Apply max-trick to one uint4 (8 fp16) with 8 gmm half2 entries (m0,m1).
__device__ __forceinline__ uint4 maxg_apply(uint4 xv, uint4 m0, uint4 m1) {
    uint32_t out[4];
    const uint32_t* xw  = (const uint32_t*)&xv;
    const uint32_t* mw0 = (const uint32_t*)&m0;
    const uint32_t* mw1 = (const uint32_t*)&m1;
    #pragma unroll
    for (int j = 0; j < 4; ++j) {
        const uint32_t ga = (j < 2) ? mw0[2 * j]     : mw1[2 * j - 4];
        const uint32_t gb = (j < 2) ? mw0[2 * j + 1] : mw1[2 * j - 3];
        const __half2 x2 = *(const __half2*)&xw[j];
        const __half2 g0 = *(const __half2*)&ga;   // (gmax_d, gmin_d)
        const __half2 g1 = *(const __half2*)&gb;
        const float x0 = __low2float(x2), x1 = __high2float(x2);
        const float s0 = (x0 >= 0.f) ? __low2float(g0) : __high2float(g0);
        const float s1 = (x1 >= 0.f) ? __low2float(g1) : __high2float(g1);
        const __half2 r = __floats2half2_rn(x0 * s0, x1 * s1);
        out[j] = *(const uint32_t*)&r;
    }
    return *(const uint4*)out;
}

// ---------------------------------------------------------------------------
// Fused QKV+S1 GEMM (unchanged).
// ---------------------------------------------------------------------------
__global__ __launch_bounds__(256, 2) void gemm_qkvs(
    const __half* __restrict__ A, const __half* __restrict__ B,
    const float* __restrict__ bq, const float* __restrict__ bk,
    const float* __restrict__ bv, const float* __restrict__ b1,
    const float* __restrict__ mask,
    __half* __restrict__ Q, __half* __restrict__ K, __half* __restrict__ V,
    float* __restrict__ S1)
{
    extern __shared__ char smem[];
    const uint32_t sbase = smem_u32(smem);
    const int tid  = threadIdx.x;
    const int lane = tid & 31;
    const int wid  = tid >> 5;
    const int wm   = wid & 3;
    const int wn   = wid >> 2;
    const int brow = blockIdx.y * 128;
    const int bcol = blockIdx.x * 128;
    const int which = blockIdx.x >> 3;
    const int bcl   = bcol & (DM - 1);
    const float* bias = which == 0 ? bq : which == 1 ? bk : which == 2 ? bv : b1;

    const int lrow  = tid >> 1;
    const int lhalf = tid & 1;
    const __half* gA = A + (size_t)(brow + lrow) * DM + lhalf * 32;
    const __half* gB = B + (size_t)(bcol + lrow) * DM + lhalf * 32;
    uint32_t soff[4];
    #pragma unroll
    for (int i = 0; i < 4; ++i)
        soff[i] = SWZ(lrow * 128 + lhalf * 64 + i * 16);

    float acc[2][8][4];
    #pragma unroll
    for (int mi = 0; mi < 2; ++mi)
        #pragma unroll
        for (int nt = 0; nt < 8; ++nt)
            #pragma unroll
            for (int r = 0; r < 4; ++r) acc[mi][nt][r] = 0.f;

    const int frow = lane & 15;
    const int fcol = (lane >> 4) << 4;

    {
        #pragma unroll
        for (int i = 0; i < 4; ++i) {
            CP_ASYNC16(sbase +         soff[i], gA + i * 8);
            CP_ASYNC16(sbase + 16384 + soff[i], gB + i * 8);
        }
        CP_COMMIT();
    }

    #pragma unroll 1
    for (int c = 0; c < 16; ++c) {
        const int s = c & 1;
        if (c + 1 < 16) {
            const uint32_t sb = sbase + ((c + 1) & 1) * STG_BIG;
            const size_t ko = (size_t)(c + 1) * BK;
            #pragma unroll
            for (int i = 0; i < 4; ++i) {
                CP_ASYNC16(sb +         soff[i], gA + ko + i * 8);
                CP_ASYNC16(sb + 16384 + soff[i], gB + ko + i * 8);
            }
            CP_COMMIT();
            CP_WAIT(1);
        } else {
            CP_WAIT(0);
        }
        __syncthreads();

        const uint32_t stg = sbase + s * STG_BIG;
        #pragma unroll
        for (int ks = 0; ks < 4; ++ks) {
            const uint32_t kb = ks * 32 + fcol;
            uint32_t a_r[2][4];
            #pragma unroll
            for (int mi = 0; mi < 2; ++mi) {
                const uint32_t o = SWZ((wm * 32 + mi * 16 + frow) * 128 + kb);
                LDMX4(a_r[mi], stg + o);
            }
            uint32_t b_r[4][4];
            #pragma unroll
            for (int nt2 = 0; nt2 < 4; ++nt2) {
                const uint32_t o = SWZ((wn * 64 + nt2 * 16 + frow) * 128 + kb);
                LDMX4(b_r[nt2], stg + 16384 + o);
            }
            #pragma unroll
            for (int mi = 0; mi < 2; ++mi)
                #pragma unroll
                for (int nt = 0; nt < 8; ++nt)
                    MMA_F16(acc[mi][nt], a_r[mi], b_r[nt >> 1][nt & 1], b_r[nt >> 1][(nt & 1) + 2]);
        }
        __syncthreads();
    }

    const int er = brow + wm * 32 + (lane >> 2);
    const int ec = bcl + wn * 64 + (lane & 3) * 2;
    if (which < 3) {
        __half* Ch = which == 0 ? Q : which == 1 ? K : V;
        #pragma unroll
        for (int mi = 0; mi < 2; ++mi) {
            #pragma unroll
            for (int nt = 0; nt < 8; ++nt) {
                const int row = er + mi * 16;
                const int col = ec + nt * 8;
                const float b0 = bias[col], b1v = bias[col + 1];
                *(__half2*)(Ch + (size_t)row * DM + col) =
                    __floats2half2_rn(acc[mi][nt][0] * WUNSCALE + b0,
                                      acc[mi][nt][1] * WUNSCALE + b1v);
                *(__half2*)(Ch + (size_t)(row + 8) * DM + col) =
                    __floats2half2_rn(acc[mi][nt][2] * WUNSCALE + b0,
                                      acc[mi][nt][3] * WUNSCALE + b1v);
            }
        }
    } else if (wn == 0) {
        #pragma unroll
        for (int mi = 0; mi < 2; ++mi) {
            #pragma unroll
            for (int nt = 0; nt < 8; ++nt) {
                const int row = er + mi * 16;
                const int col = (nt * 8 + (lane & 3) * 2);
                const float b0 = bias[col], b1v = bias[col + 1];
                const float m0 = mask[row], m1 = mask[row + 8];
                S1[(size_t)row * HG + col] =
                    __expf((acc[mi][nt][0] * WUNSCALE + b0) * INV_SCALE + m0);
                S1[(size_t)row * HG + col + 1] =
                    __expf((acc[mi][nt][1] * WUNSCALE + b1v) * INV_SCALE + m0);
                S1[(size_t)(row + 8) * HG + col] =
                    __expf((acc[mi][nt][2] * WUNSCALE + b0) * INV_SCALE + m1);
                S1[(size_t)(row + 8) * HG + col + 1] =
                    __expf((acc[mi][nt][3] * WUNSCALE + b1v) * INV_SCALE + m1);
            }
        }
    }
}

// ---------------------------------------------------------------------------
// Final GEMM, fused u: X staged via cp.async, converted IN PLACE (async X).
// out = (vh*sel(gmm2)) @ WtT + bt + qh
// ---------------------------------------------------------------------------
#define GMM_OFF (2 * STG_BIG)
#define SMEM_BIGF (2 * STG_BIG + 4096)

__global__ __launch_bounds__(256, 2) void gemm_hmma_f(
    const __half* __restrict__ X, const __half2* __restrict__ gmm,
    const __half* __restrict__ B,
    const float* __restrict__ bias, const __half* __restrict__ addv,
    float* __restrict__ C)
{
    extern __shared__ char smem[];
    const uint32_t sbase = smem_u32(smem);
    const int tid  = threadIdx.x;
    const int lane = tid & 31;
    const int wid  = tid >> 5;
    const int wm   = wid & 3;
    const int wn   = wid >> 2;
    const int brow = blockIdx.y * 128;
    const int bcol = blockIdx.x * 128;
    const int bb   = brow >> 12;

    const int lrow  = tid >> 1;
    const int lhalf = tid & 1;
    const __half* gX = X + (size_t)(brow + lrow) * DM + lhalf * 32;
    const __half* gB = B + (size_t)(bcol + lrow) * DM + lhalf * 32;
    uint32_t soff[4];
    #pragma unroll
    for (int i = 0; i < 4; ++i)
        soff[i] = SWZ(lrow * 128 + lhalf * 64 + i * 16);

    // one-time gmm slice load: 4KB
    *(uint4*)(smem + GMM_OFF + tid * 16) =
        ((const uint4*)(gmm + (size_t)bb * NH * HD))[tid];

    // prologue: X + B chunk 0 (both async)
    {
        #pragma unroll
        for (int i = 0; i < 4; ++i) {
            CP_ASYNC16(sbase +         soff[i], gX + i * 8);
            CP_ASYNC16(sbase + 16384 + soff[i], gB + i * 8);
        }
        CP_COMMIT();
    }
    __syncthreads();   // gmm visible

    float acc[2][8][4];
    #pragma unroll
    for (int mi = 0; mi < 2; ++mi)
        #pragma unroll
        for (int nt = 0; nt < 8; ++nt)
            #pragma unroll
            for (int r = 0; r < 4; ++r) acc[mi][nt][r] = 0.f;

    const int frow = lane & 15;
    const int fcol = (lane >> 4) << 4;
    const uint32_t gmo = GMM_OFF + lhalf * 128;

    #pragma unroll 1
    for (int c = 0; c < 16; ++c) {
        const int s = c & 1;
        if (c + 1 < 16) {
            const uint32_t sb = sbase + ((c + 1) & 1) * STG_BIG;
            const size_t ko = (size_t)(c + 1) * BK;
            #pragma unroll
            for (int i = 0; i < 4; ++i) {
                CP_ASYNC16(sb +         soff[i], gX + ko + i * 8);
                CP_ASYNC16(sb + 16384 + soff[i], gB + ko + i * 8);
            }
            CP_COMMIT();
            CP_WAIT(1);
        } else {
            CP_WAIT(0);
        }

        // in-place convert: own cp.async data is visible after wait
        {
            const uint32_t go = gmo + c * 256;
            char* sA = smem + s * STG_BIG;
            #pragma unroll
            for (int i = 0; i < 4; ++i) {
                const uint4 xv = *(const uint4*)(sA + soff[i]);
                const uint4 m0 = *(const uint4*)(smem + go + i * 32);
                const uint4 m1 = *(const uint4*)(smem + go + i * 32 + 16);
                *(uint4*)(sA + soff[i]) = maxg_apply(xv, m0, m1);
            }
        }
        __syncthreads();

        const uint32_t stg = sbase + s * STG_BIG;
        #pragma unroll
        for (int ks = 0; ks < 4; ++ks) {
            const uint32_t kb = ks * 32 + fcol;
            uint32_t a_r[2][4];
            #pragma unroll
            for (int mi = 0; mi < 2; ++mi) {
                const uint32_t o = SWZ((wm * 32 + mi * 16 + frow) * 128 + kb);
                LDMX4(a_r[mi], stg + o);
            }
            uint32_t b_r[4][4];
            #pragma unroll
            for (int nt2 = 0; nt2 < 4; ++nt2) {
                const uint32_t o = SWZ((wn * 64 + nt2 * 16 + frow) * 128 + kb);
                LDMX4(b_r[nt2], stg + 16384 + o);
            }
            #pragma unroll
            for (int mi = 0; mi < 2; ++mi)
                #pragma unroll
                for (int nt = 0; nt < 8; ++nt)
                    MMA_F16(acc[mi][nt], a_r[mi], b_r[nt >> 1][nt & 1], b_r[nt >> 1][(nt & 1) + 2]);
        }
        __syncthreads();
    }

    const int er = brow + wm * 32 + (lane >> 2);
    const int ec = bcol + wn * 64 + (lane & 3) * 2;
    #pragma unroll
    for (int mi = 0; mi < 2; ++mi) {
        #pragma unroll
        for (int nt = 0; nt < 8; ++nt) {
            const int row = er + mi * 16;
            const int col = ec + nt * 8;
            const float b0 = bias[col], b1v = bias[col + 1];
            const float2 f0 = __half22float2(*(const __half2*)(addv + (size_t)row * DM + col));
            const float2 f1 = __half22float2(*(const __half2*)(addv + (size_t)(row + 8) * DM + col));
            *(float2*)(C + (size_t)row * DM + col) = make_float2(
                acc[mi][nt][0] * WUNSCALE + b0 + f0.x,
                acc[mi][nt][1] * WUNSCALE + b1v + f0.y);
            *(float2*)(C + (size_t)(row + 8) * DM + col) = make_float2(
                acc[mi][nt][2] * WUNSCALE + b0 + f1.x,
                acc[mi][nt][3] * WUNSCALE + b1v + f1.y);
        }
    }
}

// ---------------------------------------------------------------------------
// N=64 GEMM, fused qk: async X + in-place convert; ksc epilogue.
// ---------------------------------------------------------------------------
#define STG_N64 24576
#define GMM_OFF64 (2 * STG_N64)
#define SMEM_N64F (2 * STG_N64 + 4096)

__global__ __launch_bounds__(256, 2) void gemm_n64_f(
    const __half* __restrict__ X, const __half2* __restrict__ gmm,
    const __half* __restrict__ B,
    const float* __restrict__ bias, const float* __restrict__ mask,
    float* __restrict__ C)
{
    extern __shared__ char smem[];
    const uint32_t sbase = smem_u32(smem);
    const int tid  = threadIdx.x;
    const int lane = tid & 31;
    const int wid  = tid >> 5;
    const int wm   = wid & 3;
    const int wn   = wid >> 2;
    const int brow = blockIdx.x * 128;
    const int bb   = brow >> 12;

    const int lrow  = tid >> 1;
    const int lhalf = tid & 1;
    const __half* gX = X + (size_t)(brow + lrow) * DM + lhalf * 32;
    uint32_t aoff[4];
    #pragma unroll
    for (int i = 0; i < 4; ++i)
        aoff[i] = SWZ(lrow * 128 + lhalf * 64 + i * 16);
    const int  brw   = (tid & 127) >> 1;
    const int  bhalf = tid & 1;
    const bool bldr  = tid < 128;
    const __half* gB = B + (size_t)brw * DM + bhalf * 32;
    uint32_t boff[4];
    #pragma unroll
    for (int i = 0; i < 4; ++i)
        boff[i] = SWZ(brw * 128 + bhalf * 64 + i * 16);

    *(uint4*)(smem + GMM_OFF64 + tid * 16) =
        ((const uint4*)(gmm + (size_t)bb * NH * HD))[tid];

    {
        #pragma unroll
        for (int i = 0; i < 4; ++i) {
            CP_ASYNC16(sbase + aoff[i], gX + i * 8);
            if (bldr) CP_ASYNC16(sbase + 16384 + boff[i], gB + i * 8);
        }
        CP_COMMIT();
    }
    __syncthreads();

    float acc[2][4][4];
    #pragma unroll
    for (int mi = 0; mi < 2; ++mi)
        #pragma unroll
        for (int nt = 0; nt < 4; ++nt)
            #pragma unroll
            for (int r = 0; r < 4; ++r) acc[mi][nt][r] = 0.f;

    const int frow = lane & 15;
    const int fcol = (lane >> 4) << 4;
    const uint32_t gmo = GMM_OFF64 + lhalf * 128;

    #pragma unroll 1
    for (int c = 0; c < 16; ++c) {
        const int s = c & 1;
        if (c + 1 < 16) {
            const uint32_t sb = sbase + ((c + 1) & 1) * STG_N64;
            const size_t ko = (size_t)(c + 1) * BK;
            #pragma unroll
            for (int i = 0; i < 4; ++i) {
                CP_ASYNC16(sb + aoff[i], gX + ko + i * 8);
                if (bldr) CP_ASYNC16(sb + 16384 + boff[i], gB + ko + i * 8);
            }
            CP_COMMIT();
            CP_WAIT(1);
        } else {
            CP_WAIT(0);
        }

        {
            const uint32_t go = gmo + c * 256;
            char* sA = smem + s * STG_N64;
            #pragma unroll
            for (int i = 0; i < 4; ++i) {
                const uint4 xv = *(const uint4*)(sA + aoff[i]);
                const uint4 m0 = *(const uint4*)(smem + go + i * 32);
                const uint4 m1 = *(const uint4*)(smem + go + i * 32 + 16);
                *(uint4*)(sA + aoff[i]) = maxg_apply(xv, m0, m1);
            }
        }
        __syncthreads();

        const uint32_t stg = sbase + s * STG_N64;
        #pragma unroll
        for (int ks = 0; ks < 4; ++ks) {
            const uint32_t kb = ks * 32 + fcol;
            uint32_t a_r[2][4];
            #pragma unroll
            for (int mi = 0; mi < 2; ++mi) {
                const uint32_t o = SWZ((wm * 32 + mi * 16 + frow) * 128 + kb);
                LDMX4(a_r[mi], stg + o);
            }
            uint32_t b_r[2][4];
            #pragma unroll
            for (int nt2 = 0; nt2 < 2; ++nt2) {
                const uint32_t o = SWZ((wn * 32 + nt2 * 16 + frow) * 128 + kb);
                LDMX4(b_r[nt2], stg + 16384 + o);
            }
            #pragma unroll
            for (int mi = 0; mi < 2; ++mi)
                #pragma unroll
                for (int nt = 0; nt < 4; ++nt)
                    MMA_F16(acc[mi][nt], a_r[mi], b_r[nt >> 1][nt & 1], b_r[nt >> 1][(nt & 1) + 2]);
        }
        __syncthreads();
    }

    const int er = brow + wm * 32 + (lane >> 2);
    const int ec = wn * 32 + (lane & 3) * 2;
    #pragma unroll
    for (int mi = 0; mi < 2; ++mi) {
        #pragma unroll
        for (int nt = 0; nt < 4; ++nt) {
            const int row = er + mi * 16;
            const int col = ec + nt * 8;
            const float b0 = bias[col], b1v = bias[col + 1];
            const float m0 = mask[row], m1 = mask[row + 8];
            *(float2*)(C + (size_t)row * HG + col) = make_float2(
                (acc[mi][nt][0] * WUNSCALE + b0) * INV_SCALE + m0,
                (acc[mi][nt][1] * WUNSCALE + b1v) * INV_SCALE + m0);
            *(float2*)(C + (size_t)(row + 8) * HG + col) = make_float2(
                (acc[mi][nt][2] * WUNSCALE + b0) * INV_SCALE + m1,
                (acc[mi][nt][3] * WUNSCALE + b1v) * INV_SCALE + m1);
        }
    }
}

// ---------------------------------------------------------------------------
// Fused gsum + colsum + gminmax.  One CTA per (b,h), 512 threads, no atomics.
// tid = q(2b) | g(2b) | dp(5b): n-quarter, group, d-pair.
// gmm[b,h,d] = (max_g, min_g) of [sum_n w*x] (optionally / sum_n w).
// ---------------------------------------------------------------------------
__global__ __launch_bounds__(512, 2) void gsum_fused(
    const __half* __restrict__ x, const float* __restrict__ w,
    int normalize, __half2* __restrict__ gmm)
{
    const int bh = blockIdx.x;               // b*NH + h
    const int b = bh >> 4, h = bh & 15;
    const int qn = threadIdx.x >> 7;         // 0..3 (n-quarter)
    const int g  = (threadIdx.x >> 5) & 3;
    const int dp = threadIdx.x & 31;         // d-pair

    const __half2* xp = (const __half2*)(x
        + ((size_t)b * SEQ + qn * 1024) * DM + h * HD + dp * 2);
    const float* wp = w + ((size_t)b * SEQ + qn * 1024) * HG + h * NG + g;

    float ax0 = 0.f, ay0 = 0.f, ax1 = 0.f, ay1 = 0.f;
    float c0 = 0.f, c1 = 0.f;
    #pragma unroll 2
    for (int n = 0; n < 1024; n += 2) {
        const float w0 = wp[(size_t)(n + 0) * HG];
        const float w1 = wp[(size_t)(n + 1) * HG];
        const float2 v0 = __half22float2(xp[(size_t)(n + 0) * (DM / 2)]);
        const float2 v1 = __half22float2(xp[(size_t)(n + 1) * (DM / 2)]);
        ax0 = fmaf(v0.x, w0, ax0); ay0 = fmaf(v0.y, w0, ay0);
        ax1 = fmaf(v1.x, w1, ax1); ay1 = fmaf(v1.y, w1, ay1);
        c0 += w0; c1 += w1;
    }

    __shared__ float sg[4][4][64];   // [quarter][g][d]
    __shared__ float sc[4][4];       // [quarter][g]
    sg[qn][g][dp * 2]     = ax0 + ax1;
    sg[qn][g][dp * 2 + 1] = ay0 + ay1;
    if (dp == 0) sc[qn][g] = c0 + c1;
    __syncthreads();

    if (threadIdx.x < 256) {
        const int gg = threadIdx.x >> 6, dd = threadIdx.x & 63;
        float v = (sg[0][gg][dd] + sg[1][gg][dd])
                + (sg[2][gg][dd] + sg[3][gg][dd]);
        if (normalize) {
            const float cs = (sc[0][gg] + sc[1][gg]) + (sc[2][gg] + sc[3][gg]);
            v /= cs;
        }
        __syncthreads();
        sg[0][gg][dd] = v;
    } else {
        __syncthreads();
    }
    __syncthreads();

    if (threadIdx.x < 64) {
        const int dd = threadIdx.x;
        const float v0 = sg[0][0][dd], v1 = sg[0][1][dd];
        const float v2 = sg[0][2][dd], v3 = sg[0][3][dd];
        gmm[(size_t)bh * HD + dd] = __floats2half2_rn(
            fmaxf(fmaxf(v0, v1), fmaxf(v2, v3)),
            fminf(fminf(v0, v1), fminf(v2, v3)));
    }
}

// ---------------------------------------------------------------------------
// prep kernels
// ---------------------------------------------------------------------------
__global__ __launch_bounds__(256) void tofp16(
    const float4* __restrict__ x, __half2* __restrict__ o)
{
    const size_t i = (size_t)blockIdx.x * 256 + threadIdx.x;
    const float4 v = x[i];
    o[2 * i]     = __floats2half2_rn(v.x, v.y);
    o[2 * i + 1] = __floats2half2_rn(v.z, v.w);
}

__global__ __launch_bounds__(256) void wconv4(
    const float* __restrict__ W0, const float* __restrict__ W1,
    const float* __restrict__ W2, const float* __restrict__ W3,
    __half* __restrict__ Tcat, __half* __restrict__ Twt)
{
    __shared__ float tile[32][33];
    const int z = blockIdx.z;
    const float* W = z == 0 ? W0 : z == 1 ? W1 : z == 2 ? W2 : W3;
    __half* Tz = z < 3 ? Tcat + (size_t)z * DM * DM : Twt;
    const int bn = blockIdx.x * 32;
    const int bk = blockIdx.y * 32;
    const int x = threadIdx.x;
    const int y = threadIdx.y;
    #pragma unroll
    for (int i = 0; i < 32; i += 8)
        tile[y + i][x] = W[(size_t)(bk + y + i) * DM + bn + x];
    __syncthreads();
    #pragma unroll
    for (int i = 0; i < 32; i += 8)
        Tz[(size_t)(bn + y + i) * DM + bk + x] =
            __float2half_rn(tile[x][y + i] * WSCALE);
}

__global__ __launch_bounds__(256) void wconv_t(
    const float* __restrict__ W, __half* __restrict__ T, int ncols)
{
    __shared__ float tile[32][33];
    const int bn = blockIdx.x * 32;
    const int bk = blockIdx.y * 32;
    const int x = threadIdx.x;
    const int y = threadIdx.y;
    #pragma unroll
    for (int i = 0; i < 32; i += 8)
        tile[y + i][x] = W[(size_t)(bk + y + i) * ncols + bn + x];
    __syncthreads();
    #pragma unroll
    for (int i = 0; i < 32; i += 8)
        T[(size_t)(bn + y + i) * DM + bk + x] =
            __float2half_rn(tile[x][y + i] * WSCALE);
}

__global__ __launch_bounds__(256) void sgemm_small(
    const float* __restrict__ A, const float* __restrict__ W,
    const float* __restrict__ bias, float* __restrict__ C)
{
    __shared__ __align__(16) float As[16][64];
    __shared__ __align__(16) float Bs[16][64];
    const int tid  = threadIdx.x;
    const int brow = blockIdx.y * 64;
    const int arow = tid >> 2;
    const int akof = (tid & 3) * 4;
    const int bkr  = tid >> 4;
    const int bc4  = (tid & 15) * 4;
    const int trow = (tid >> 4) * 4;
    const int tcol = (tid & 15) * 4;

    float acc[4][4];
    #pragma unroll
    for (int i = 0; i < 4; i++)
        #pragma unroll
        for (int j = 0; j < 4; j++) acc[i][j] = 0.f;

    const float* Ab = A + (size_t)(brow + arow) * DM + akof;
    const float* Wb = W + (size_t)bkr * HG + bc4;

    for (int k0 = 0; k0 < DM; k0 += 16) {
        float4 av = *(const float4*)(Ab + k0);
        As[akof + 0][arow] = av.x;
        As[akof + 1][arow] = av.y;
        As[akof + 2][arow] = av.z;
        As[akof + 3][arow] = av.w;
        float4 bv = *(const float4*)(Wb + (size_t)k0 * HG);
        *(float4*)&Bs[bkr][bc4] = bv;
        __syncthreads();
        #pragma unroll
        for (int kk = 0; kk < 16; kk++) {
            float4 a0 = *(const float4*)&As[kk][trow];
            float4 b0 = *(const float4*)&Bs[kk][tcol];
            float ar[4] = {a0.x, a0.y, a0.z, a0.w};
            float br[4] = {b0.x, b0.y, b0.z, b0.w};
            #pragma unroll
            for (int i = 0; i < 4; i++)
                #pragma unroll
                for (int j = 0; j < 4; j++)
                    acc[i][j] = fmaf(ar[i], br[j], acc[i][j]);
        }
        __syncthreads();
    }
    #pragma unroll
    for (int i = 0; i < 4; i++)
        #pragma unroll
        for (int j = 0; j < 4; j++)
            C[(size_t)(brow + trow + i) * HG + tcol + j] = acc[i][j] + bias[tcol + j];
}

__global__ void bias_comb(const float* __restrict__ bq,
                          const float* __restrict__ Wqa,
                          const float* __restrict__ bqa,
                          float* __restrict__ b1)
{
    __shared__ float part[4][HG];
    const int j = threadIdx.x & 63;
    const int p = threadIdx.x >> 6;
    float s = 0.f;
    for (int i = p * 256; i < (p + 1) * 256; ++i)
        s = fmaf(bq[i], Wqa[(size_t)i * HG + j], s);
    part[p][j] = s;
    __syncthreads();
    if (p == 0)
        b1[j] = bqa[j] + ((part[0][j] + part[1][j]) + (part[2][j] + part[3][j]));
}

// zero the ws1 pad rows (64..127 of the 4th wcat section): 64*1024 halves
__global__ __launch_bounds__(256) void zero_pad(uint4* __restrict__ pad)
{
    pad[blockIdx.x * 256 + threadIdx.x] = make_uint4(0, 0, 0, 0);
}

// ---------------------------------------------------------------------------
// Launch
// ---------------------------------------------------------------------------
extern "C" void kernel_launch(void* const* d_in, const int* in_sizes, int n_in,
                              void* d_out, int out_size)
{
    const float* hs   = (const float*)d_in[0];
    const float* mask = (const float*)d_in[1];
    const float* Wq   = (const float*)d_in[2];
    const float* bq   = (const float*)d_in[3];
    const float* Wqa  = (const float*)d_in[4];
    const float* bqa  = (const float*)d_in[5];
    const float* Wk   = (const float*)d_in[6];
    const float* bk   = (const float*)d_in[7];
    const float* Wka  = (const float*)d_in[8];
    const float* bka  = (const float*)d_in[9];
    const float* Wv   = (const float*)d_in[10];
    const float* bv   = (const float*)d_in[11];
    const float* Wt   = (const float*)d_in[12];
    const float* bt   = (const float*)d_in[13];
    float* out = (float*)d_out;

    float *s1, *s2, *b1, *zv;
    __half2 *gmm1, *gmm2;
    __half *qh, *kh, *vh, *ah, *wcat, *wt, *ws2;
    cudaGetSymbolAddress((void**)&s1,   g_s1);
    cudaGetSymbolAddress((void**)&s2,   g_s2);
    cudaGetSymbolAddress((void**)&b1,   g_b1);
    cudaGetSymbolAddress((void**)&zv,   g_zero);
    cudaGetSymbolAddress((void**)&gmm1, g_gmm1);
    cudaGetSymbolAddress((void**)&gmm2, g_gmm2);
    cudaGetSymbolAddress((void**)&qh,   g_qh);
    cudaGetSymbolAddress((void**)&kh,   g_kh);
    cudaGetSymbolAddress((void**)&vh,   g_vh);
    cudaGetSymbolAddress((void**)&ah,   g_ah);
    cudaGetSymbolAddress((void**)&wcat, g_wcat);
    cudaGetSymbolAddress((void**)&wt,   g_wt);
    cudaGetSymbolAddress((void**)&ws2,  g_ws2);

    cudaFuncSetAttribute(gemm_qkvs,   cudaFuncAttributeMaxDynamicSharedMemorySize, SMEM_BIG);
    cudaFuncSetAttribute(gemm_hmma_f, cudaFuncAttributeMaxDynamicSharedMemorySize, SMEM_BIGF);
    cudaFuncSetAttribute(gemm_n64_f,  cudaFuncAttributeMaxDynamicSharedMemorySize, SMEM_N64F);

    const size_t WSZ = (size_t)DM * DM;
    __half* ws1 = wcat + 3 * WSZ;
    uint4* pad = (uint4*)(wcat + 3 * WSZ + 64 * DM);   // 64 rows x 1024 halves

    dim3 bW(32, 8);

    // --- prep ---
    zero_pad<<<(64 * DM / 8) / 256, 256>>>(pad);
    wconv4<<<dim3(DM / 32, DM / 32, 4), bW>>>(Wq, Wk, Wv, Wt, wcat, wt);
    sgemm_small<<<dim3(1, DM / 64), 256>>>(Wq, Wqa, zv, s2);
    wconv_t<<<dim3(HG / 32, DM / 32), bW>>>(s2, ws1, HG);
    bias_comb<<<1, 256>>>(bq, Wqa, bqa, b1);
    wconv_t<<<dim3(HG / 32, DM / 32), bW>>>(Wka, ws2, HG);
    tofp16<<<(MROWS * DM / 4) / 256, 256>>>((const float4*)hs, (__half2*)ah);

    // --- fused q,k,v,s1 projection ---
    gemm_qkvs<<<dim3(25, MROWS / 128), 256, SMEM_BIG>>>(
        ah, wcat, bq, bk, bv, b1, mask, qh, kh, vh, s1);

    // --- q-attention reduction (fused gsum+colsum+minmax) ---
    gsum_fused<<<BATCH * NH, 512>>>(qh, s1, 1, gmm1);

    // --- ksc (fused qk from kh+gmm1) -> k-side reduction ---
    gemm_n64_f<<<MROWS / 128, 256, SMEM_N64F>>>(kh, gmm1, ws2, bka, mask, s2);
    gsum_fused<<<BATCH * NH, 512>>>(kh, s2, 0, gmm2);

    // --- out = (fused u from vh+gmm2) @ Wt + bt + qh ---
    gemm_hmma_f<<<dim3(DM / 128, MROWS / 128), 256, SMEM_BIGF>>>(
        vh, gmm2, wt, bt, qh, out);
}

// round 12
// speedup vs baseline: 1.0074x; 1.0071x over previous
#include <cuda_runtime.h>
#include <cuda_fp16.h>
#include <cstdint>

// Problem constants
#define BATCH 8
#define SEQ   4096
#define DM    1024
#define NH    16
#define NG    4
#define HD    64
#define HG    (NH*NG)          // 64
#define MROWS (BATCH*SEQ)      // 32768
#define INV_SCALE 0.125f       // 1/sqrt(64)
#define WSCALE 1024.0f
#define WUNSCALE (1.0f/1024.0f)

// ---------------------------------------------------------------------------
// Scratch (device globals)
// ---------------------------------------------------------------------------
__device__ float g_s1[MROWS * HG];              // exp(q-scores)
__device__ float g_s2[MROWS * HG];              // ksc; WqWqa fp32 tmp during prep
__device__ float g_b1[HG];                      // bq@Wqa + bqa
__device__ float g_zero[HG];
__device__ __align__(256) __half2 g_gmm1[BATCH * NH * HD];  // (gmax,gmin) of gq/cs
__device__ __align__(256) __half2 g_gmm2[BATCH * NH * HD];  // (gmax,gmin) of gk
__device__ __align__(256) __half g_qh[MROWS * DM];
__device__ __align__(256) __half g_kh[MROWS * DM];
__device__ __align__(256) __half g_vh[MROWS * DM];
__device__ __align__(256) __half g_ah[MROWS * DM];            // hs fp16
__device__ __align__(256) __half g_wcat[(3 * DM + 128) * DM]; // WqT|WkT|WvT|ws1pad
__device__ __align__(256) __half g_wt[DM * DM];               // WtT
__device__ __align__(256) __half g_ws2[HG * DM];              // WkaT

// ---------------------------------------------------------------------------
// PTX helpers (plain sm_103-safe)
// ---------------------------------------------------------------------------
__device__ __forceinline__ uint32_t smem_u32(const void* p) {
    uint32_t a;
    asm("{ .reg .u64 t; cvta.to.shared.u64 t, %1; cvt.u32.u64 %0, t; }"
        : "=r"(a) : "l"(p));
    return a;
}
#define CP_ASYNC16(s, g) \
    asm volatile("cp.async.cg.shared.global [%0], [%1], 16;" :: "r"(s), "l"(g))
#define CP_COMMIT() asm volatile("cp.async.commit_group;" ::: "memory")
#define CP_WAIT(n)  asm volatile("cp.async.wait_group %0;" :: "n"(n) : "memory")
#define LDMX4(r, addr) \
    asm volatile("ldmatrix.sync.aligned.m8n8.x4.shared.b16 {%0,%1,%2,%3}, [%4];" \
        : "=r"((r)[0]), "=r"((r)[1]), "=r"((r)[2]), "=r"((r)[3]) : "r"(addr))
#define MMA_F16(d, a, b0, b1) \
    asm volatile("mma.sync.aligned.m16n8k16.row.col.f32.f16.f16.f32 " \
        "{%0,%1,%2,%3}, {%4,%5,%6,%7}, {%8,%9}, {%0,%1,%2,%3};" \
        : "+f"((d)[0]), "+f"((d)[1]), "+f"((d)[2]), "+f"((d)[3]) \
        : "r"((a)[0]), "r"((a)[1]), "r"((a)[2]), "r"((a)[3]), "r"(b0), "r"(b1))

#define SWZ(o) ((uint32_t)(o) ^ ((((uint32_t)(o)) >> 3) & 0x70))

#define BK 64
#define STG_BIG 32768
#define SMEM_BIG (2 * STG_BIG)

// Apply max-trick to one uint4 (8 fp16) with 8 gmm half2 entries (m0,m1).
__device__ __forceinline__ uint4 maxg_apply(uint4 xv, uint4 m0, uint4 m1) {
    uint32_t out[4];
    const uint32_t* xw  = (const uint32_t*)&xv;
    const uint32_t* mw0 = (const uint32_t*)&m0;
    const uint32_t* mw1 = (const uint32_t*)&m1;
    #pragma unroll
    for (int j = 0; j < 4; ++j) {
        const uint32_t ga = (j < 2) ? mw0[2 * j]     : mw1[2 * j - 4];
        const uint32_t gb = (j < 2) ? mw0[2 * j + 1] : mw1[2 * j - 3];
        const __half2 x2 = *(const __half2*)&xw[j];
        const __half2 g0 = *(const __half2*)&ga;   // (gmax_d, gmin_d)
        const __half2 g1 = *(const __half2*)&gb;
        const float x0 = __low2float(x2), x1 = __high2float(x2);
        const float s0 = (x0 >= 0.f) ? __low2float(g0) : __high2float(g0);
        const float s1 = (x1 >= 0.f) ? __low2float(g1) : __high2float(g1);
        const __half2 r = __floats2half2_rn(x0 * s0, x1 * s1);
        out[j] = *(const uint32_t*)&r;
    }
    return *(const uint4*)out;
}

// ---------------------------------------------------------------------------
// Fused QKV+S1 GEMM (unchanged).
// ---------------------------------------------------------------------------
__global__ __launch_bounds__(256, 2) void gemm_qkvs(
    const __half* __restrict__ A, const __half* __restrict__ B,
    const float* __restrict__ bq, const float* __restrict__ bk,
    const float* __restrict__ bv, const float* __restrict__ b1,
    const float* __restrict__ mask,
    __half* __restrict__ Q, __half* __restrict__ K, __half* __restrict__ V,
    float* __restrict__ S1)
{
    extern __shared__ char smem[];
    const uint32_t sbase = smem_u32(smem);
    const int tid  = threadIdx.x;
    const int lane = tid & 31;
    const int wid  = tid >> 5;
    const int wm   = wid & 3;
    const int wn   = wid >> 2;
    const int brow = blockIdx.y * 128;
    const int bcol = blockIdx.x * 128;
    const int which = blockIdx.x >> 3;
    const int bcl   = bcol & (DM - 1);
    const float* bias = which == 0 ? bq : which == 1 ? bk : which == 2 ? bv : b1;

    const int lrow  = tid >> 1;
    const int lhalf = tid & 1;
    const __half* gA = A + (size_t)(brow + lrow) * DM + lhalf * 32;
    const __half* gB = B + (size_t)(bcol + lrow) * DM + lhalf * 32;
    uint32_t soff[4];
    #pragma unroll
    for (int i = 0; i < 4; ++i)
        soff[i] = SWZ(lrow * 128 + lhalf * 64 + i * 16);

    float acc[2][8][4];
    #pragma unroll
    for (int mi = 0; mi < 2; ++mi)
        #pragma unroll
        for (int nt = 0; nt < 8; ++nt)
            #pragma unroll
            for (int r = 0; r < 4; ++r) acc[mi][nt][r] = 0.f;

    const int frow = lane & 15;
    const int fcol = (lane >> 4) << 4;

    {
        #pragma unroll
        for (int i = 0; i < 4; ++i) {
            CP_ASYNC16(sbase +         soff[i], gA + i * 8);
            CP_ASYNC16(sbase + 16384 + soff[i], gB + i * 8);
        }
        CP_COMMIT();
    }

    #pragma unroll 1
    for (int c = 0; c < 16; ++c) {
        const int s = c & 1;
        if (c + 1 < 16) {
            const uint32_t sb = sbase + ((c + 1) & 1) * STG_BIG;
            const size_t ko = (size_t)(c + 1) * BK;
            #pragma unroll
            for (int i = 0; i < 4; ++i) {
                CP_ASYNC16(sb +         soff[i], gA + ko + i * 8);
                CP_ASYNC16(sb + 16384 + soff[i], gB + ko + i * 8);
            }
            CP_COMMIT();
            CP_WAIT(1);
        } else {
            CP_WAIT(0);
        }
        __syncthreads();

        const uint32_t stg = sbase + s * STG_BIG;
        #pragma unroll
        for (int ks = 0; ks < 4; ++ks) {
            const uint32_t kb = ks * 32 + fcol;
            uint32_t a_r[2][4];
            #pragma unroll
            for (int mi = 0; mi < 2; ++mi) {
                const uint32_t o = SWZ((wm * 32 + mi * 16 + frow) * 128 + kb);
                LDMX4(a_r[mi], stg + o);
            }
            uint32_t b_r[4][4];
            #pragma unroll
            for (int nt2 = 0; nt2 < 4; ++nt2) {
                const uint32_t o = SWZ((wn * 64 + nt2 * 16 + frow) * 128 + kb);
                LDMX4(b_r[nt2], stg + 16384 + o);
            }
            #pragma unroll
            for (int mi = 0; mi < 2; ++mi)
                #pragma unroll
                for (int nt = 0; nt < 8; ++nt)
                    MMA_F16(acc[mi][nt], a_r[mi], b_r[nt >> 1][nt & 1], b_r[nt >> 1][(nt & 1) + 2]);
        }
        __syncthreads();
    }

    const int er = brow + wm * 32 + (lane >> 2);
    const int ec = bcl + wn * 64 + (lane & 3) * 2;
    if (which < 3) {
        __half* Ch = which == 0 ? Q : which == 1 ? K : V;
        #pragma unroll
        for (int mi = 0; mi < 2; ++mi) {
            #pragma unroll
            for (int nt = 0; nt < 8; ++nt) {
                const int row = er + mi * 16;
                const int col = ec + nt * 8;
                const float b0 = bias[col], b1v = bias[col + 1];
                *(__half2*)(Ch + (size_t)row * DM + col) =
                    __floats2half2_rn(acc[mi][nt][0] * WUNSCALE + b0,
                                      acc[mi][nt][1] * WUNSCALE + b1v);
                *(__half2*)(Ch + (size_t)(row + 8) * DM + col) =
                    __floats2half2_rn(acc[mi][nt][2] * WUNSCALE + b0,
                                      acc[mi][nt][3] * WUNSCALE + b1v);
            }
        }
    } else if (wn == 0) {
        #pragma unroll
        for (int mi = 0; mi < 2; ++mi) {
            #pragma unroll
            for (int nt = 0; nt < 8; ++nt) {
                const int row = er + mi * 16;
                const int col = (nt * 8 + (lane & 3) * 2);
                const float b0 = bias[col], b1v = bias[col + 1];
                const float m0 = mask[row], m1 = mask[row + 8];
                S1[(size_t)row * HG + col] =
                    __expf((acc[mi][nt][0] * WUNSCALE + b0) * INV_SCALE + m0);
                S1[(size_t)row * HG + col + 1] =
                    __expf((acc[mi][nt][1] * WUNSCALE + b1v) * INV_SCALE + m0);
                S1[(size_t)(row + 8) * HG + col] =
                    __expf((acc[mi][nt][2] * WUNSCALE + b0) * INV_SCALE + m1);
                S1[(size_t)(row + 8) * HG + col + 1] =
                    __expf((acc[mi][nt][3] * WUNSCALE + b1v) * INV_SCALE + m1);
            }
        }
    }
}

// ---------------------------------------------------------------------------
// Final GEMM, fused u: X staged via cp.async, converted IN PLACE (async X).
// out = (vh*sel(gmm2)) @ WtT + bt + qh
// ---------------------------------------------------------------------------
#define GMM_OFF (2 * STG_BIG)
#define SMEM_BIGF (2 * STG_BIG + 4096)

__global__ __launch_bounds__(256, 2) void gemm_hmma_f(
    const __half* __restrict__ X, const __half2* __restrict__ gmm,
    const __half* __restrict__ B,
    const float* __restrict__ bias, const __half* __restrict__ addv,
    float* __restrict__ C)
{
    extern __shared__ char smem[];
    const uint32_t sbase = smem_u32(smem);
    const int tid  = threadIdx.x;
    const int lane = tid & 31;
    const int wid  = tid >> 5;
    const int wm   = wid & 3;
    const int wn   = wid >> 2;
    const int brow = blockIdx.y * 128;
    const int bcol = blockIdx.x * 128;
    const int bb   = brow >> 12;

    const int lrow  = tid >> 1;
    const int lhalf = tid & 1;
    const __half* gX = X + (size_t)(brow + lrow) * DM + lhalf * 32;
    const __half* gB = B + (size_t)(bcol + lrow) * DM + lhalf * 32;
    uint32_t soff[4];
    #pragma unroll
    for (int i = 0; i < 4; ++i)
        soff[i] = SWZ(lrow * 128 + lhalf * 64 + i * 16);

    // one-time gmm slice load: 4KB
    *(uint4*)(smem + GMM_OFF + tid * 16) =
        ((const uint4*)(gmm + (size_t)bb * NH * HD))[tid];

    // prologue: X + B chunk 0 (both async)
    {
        #pragma unroll
        for (int i = 0; i < 4; ++i) {
            CP_ASYNC16(sbase +         soff[i], gX + i * 8);
            CP_ASYNC16(sbase + 16384 + soff[i], gB + i * 8);
        }
        CP_COMMIT();
    }
    __syncthreads();   // gmm visible

    float acc[2][8][4];
    #pragma unroll
    for (int mi = 0; mi < 2; ++mi)
        #pragma unroll
        for (int nt = 0; nt < 8; ++nt)
            #pragma unroll
            for (int r = 0; r < 4; ++r) acc[mi][nt][r] = 0.f;

    const int frow = lane & 15;
    const int fcol = (lane >> 4) << 4;
    const uint32_t gmo = GMM_OFF + lhalf * 128;

    #pragma unroll 1
    for (int c = 0; c < 16; ++c) {
        const int s = c & 1;
        if (c + 1 < 16) {
            const uint32_t sb = sbase + ((c + 1) & 1) * STG_BIG;
            const size_t ko = (size_t)(c + 1) * BK;
            #pragma unroll
            for (int i = 0; i < 4; ++i) {
                CP_ASYNC16(sb +         soff[i], gX + ko + i * 8);
                CP_ASYNC16(sb + 16384 + soff[i], gB + ko + i * 8);
            }
            CP_COMMIT();
            CP_WAIT(1);
        } else {
            CP_WAIT(0);
        }

        // in-place convert: own cp.async data is visible after wait
        {
            const uint32_t go = gmo + c * 256;
            char* sA = smem + s * STG_BIG;
            #pragma unroll
            for (int i = 0; i < 4; ++i) {
                const uint4 xv = *(const uint4*)(sA + soff[i]);
                const uint4 m0 = *(const uint4*)(smem + go + i * 32);
                const uint4 m1 = *(const uint4*)(smem + go + i * 32 + 16);
                *(uint4*)(sA + soff[i]) = maxg_apply(xv, m0, m1);
            }
        }
        __syncthreads();

        const uint32_t stg = sbase + s * STG_BIG;
        #pragma unroll
        for (int ks = 0; ks < 4; ++ks) {
            const uint32_t kb = ks * 32 + fcol;
            uint32_t a_r[2][4];
            #pragma unroll
            for (int mi = 0; mi < 2; ++mi) {
                const uint32_t o = SWZ((wm * 32 + mi * 16 + frow) * 128 + kb);
                LDMX4(a_r[mi], stg + o);
            }
            uint32_t b_r[4][4];
            #pragma unroll
            for (int nt2 = 0; nt2 < 4; ++nt2) {
                const uint32_t o = SWZ((wn * 64 + nt2 * 16 + frow) * 128 + kb);
                LDMX4(b_r[nt2], stg + 16384 + o);
            }
            #pragma unroll
            for (int mi = 0; mi < 2; ++mi)
                #pragma unroll
                for (int nt = 0; nt < 8; ++nt)
                    MMA_F16(acc[mi][nt], a_r[mi], b_r[nt >> 1][nt & 1], b_r[nt >> 1][(nt & 1) + 2]);
        }
        __syncthreads();
    }

    const int er = brow + wm * 32 + (lane >> 2);
    const int ec = bcol + wn * 64 + (lane & 3) * 2;
    #pragma unroll
    for (int mi = 0; mi < 2; ++mi) {
        #pragma unroll
        for (int nt = 0; nt < 8; ++nt) {
            const int row = er + mi * 16;
            const int col = ec + nt * 8;
            const float b0 = bias[col], b1v = bias[col + 1];
            const float2 f0 = __half22float2(*(const __half2*)(addv + (size_t)row * DM + col));
            const float2 f1 = __half22float2(*(const __half2*)(addv + (size_t)(row + 8) * DM + col));
            *(float2*)(C + (size_t)row * DM + col) = make_float2(
                acc[mi][nt][0] * WUNSCALE + b0 + f0.x,
                acc[mi][nt][1] * WUNSCALE + b1v + f0.y);
            *(float2*)(C + (size_t)(row + 8) * DM + col) = make_float2(
                acc[mi][nt][2] * WUNSCALE + b0 + f1.x,
                acc[mi][nt][3] * WUNSCALE + b1v + f1.y);
        }
    }
}

// ---------------------------------------------------------------------------
// N=64 GEMM, fused qk: async X + in-place convert; ksc epilogue.
// ---------------------------------------------------------------------------
#define STG_N64 24576
#define GMM_OFF64 (2 * STG_N64)
#define SMEM_N64F (2 * STG_N64 + 4096)

__global__ __launch_bounds__(256, 2) void gemm_n64_f(
    const __half* __restrict__ X, const __half2* __restrict__ gmm,
    const __half* __restrict__ B,
    const float* __restrict__ bias, const float* __restrict__ mask,
    float* __restrict__ C)
{
    extern __shared__ char smem[];
    const uint32_t sbase = smem_u32(smem);
    const int tid  = threadIdx.x;
    const int lane = tid & 31;
    const int wid  = tid >> 5;
    const int wm   = wid & 3;
    const int wn   = wid >> 2;
    const int brow = blockIdx.x * 128;
    const int bb   = brow >> 12;

    const int lrow  = tid >> 1;
    const int lhalf = tid & 1;
    const __half* gX = X + (size_t)(brow + lrow) * DM + lhalf * 32;
    uint32_t aoff[4];
    #pragma unroll
    for (int i = 0; i < 4; ++i)
        aoff[i] = SWZ(lrow * 128 + lhalf * 64 + i * 16);
    const int  brw   = (tid & 127) >> 1;
    const int  bhalf = tid & 1;
    const bool bldr  = tid < 128;
    const __half* gB = B + (size_t)brw * DM + bhalf * 32;
    uint32_t boff[4];
    #pragma unroll
    for (int i = 0; i < 4; ++i)
        boff[i] = SWZ(brw * 128 + bhalf * 64 + i * 16);

    *(uint4*)(smem + GMM_OFF64 + tid * 16) =
        ((const uint4*)(gmm + (size_t)bb * NH * HD))[tid];

    {
        #pragma unroll
        for (int i = 0; i < 4; ++i) {
            CP_ASYNC16(sbase + aoff[i], gX + i * 8);
            if (bldr) CP_ASYNC16(sbase + 16384 + boff[i], gB + i * 8);
        }
        CP_COMMIT();
    }
    __syncthreads();

    float acc[2][4][4];
    #pragma unroll
    for (int mi = 0; mi < 2; ++mi)
        #pragma unroll
        for (int nt = 0; nt < 4; ++nt)
            #pragma unroll
            for (int r = 0; r < 4; ++r) acc[mi][nt][r] = 0.f;

    const int frow = lane & 15;
    const int fcol = (lane >> 4) << 4;
    const uint32_t gmo = GMM_OFF64 + lhalf * 128;

    #pragma unroll 1
    for (int c = 0; c < 16; ++c) {
        const int s = c & 1;
        if (c + 1 < 16) {
            const uint32_t sb = sbase + ((c + 1) & 1) * STG_N64;
            const size_t ko = (size_t)(c + 1) * BK;
            #pragma unroll
            for (int i = 0; i < 4; ++i) {
                CP_ASYNC16(sb + aoff[i], gX + ko + i * 8);
                if (bldr) CP_ASYNC16(sb + 16384 + boff[i], gB + ko + i * 8);
            }
            CP_COMMIT();
            CP_WAIT(1);
        } else {
            CP_WAIT(0);
        }

        {
            const uint32_t go = gmo + c * 256;
            char* sA = smem + s * STG_N64;
            #pragma unroll
            for (int i = 0; i < 4; ++i) {
                const uint4 xv = *(const uint4*)(sA + aoff[i]);
                const uint4 m0 = *(const uint4*)(smem + go + i * 32);
                const uint4 m1 = *(const uint4*)(smem + go + i * 32 + 16);
                *(uint4*)(sA + aoff[i]) = maxg_apply(xv, m0, m1);
            }
        }
        __syncthreads();

        const uint32_t stg = sbase + s * STG_N64;
        #pragma unroll
        for (int ks = 0; ks < 4; ++ks) {
            const uint32_t kb = ks * 32 + fcol;
            uint32_t a_r[2][4];
            #pragma unroll
            for (int mi = 0; mi < 2; ++mi) {
                const uint32_t o = SWZ((wm * 32 + mi * 16 + frow) * 128 + kb);
                LDMX4(a_r[mi], stg + o);
            }
            uint32_t b_r[2][4];
            #pragma unroll
            for (int nt2 = 0; nt2 < 2; ++nt2) {
                const uint32_t o = SWZ((wn * 32 + nt2 * 16 + frow) * 128 + kb);
                LDMX4(b_r[nt2], stg + 16384 + o);
            }
            #pragma unroll
            for (int mi = 0; mi < 2; ++mi)
                #pragma unroll
                for (int nt = 0; nt < 4; ++nt)
                    MMA_F16(acc[mi][nt], a_r[mi], b_r[nt >> 1][nt & 1], b_r[nt >> 1][(nt & 1) + 2]);
        }
        __syncthreads();
    }

    const int er = brow + wm * 32 + (lane >> 2);
    const int ec = wn * 32 + (lane & 3) * 2;
    #pragma unroll
    for (int mi = 0; mi < 2; ++mi) {
        #pragma unroll
        for (int nt = 0; nt < 4; ++nt) {
            const int row = er + mi * 16;
            const int col = ec + nt * 8;
            const float b0 = bias[col], b1v = bias[col + 1];
            const float m0 = mask[row], m1 = mask[row + 8];
            *(float2*)(C + (size_t)row * HG + col) = make_float2(
                (acc[mi][nt][0] * WUNSCALE + b0) * INV_SCALE + m0,
                (acc[mi][nt][1] * WUNSCALE + b1v) * INV_SCALE + m0);
            *(float2*)(C + (size_t)(row + 8) * HG + col) = make_float2(
                (acc[mi][nt][2] * WUNSCALE + b0) * INV_SCALE + m1,
                (acc[mi][nt][3] * WUNSCALE + b1v) * INV_SCALE + m1);
        }
    }
}

// ---------------------------------------------------------------------------
// Fused gsum + colsum + gminmax.  One CTA per (b,h), 512 threads, no atomics.
// tid = q(2b) | g(2b) | dp(5b): n-quarter, group, d-pair.
// gmm[b,h,d] = (max_g, min_g) of [sum_n w*x] (optionally / sum_n w).
// ---------------------------------------------------------------------------
__global__ __launch_bounds__(512, 2) void gsum_fused(
    const __half* __restrict__ x, const float* __restrict__ w,
    int normalize, __half2* __restrict__ gmm)
{
    const int bh = blockIdx.x;               // b*NH + h
    const int b = bh >> 4, h = bh & 15;
    const int qn = threadIdx.x >> 7;         // 0..3 (n-quarter)
    const int g  = (threadIdx.x >> 5) & 3;
    const int dp = threadIdx.x & 31;         // d-pair

    const __half2* xp = (const __half2*)(x
        + ((size_t)b * SEQ + qn * 1024) * DM + h * HD + dp * 2);
    const float* wp = w + ((size_t)b * SEQ + qn * 1024) * HG + h * NG + g;

    float ax0 = 0.f, ay0 = 0.f, ax1 = 0.f, ay1 = 0.f;
    float c0 = 0.f, c1 = 0.f;
    #pragma unroll 2
    for (int n = 0; n < 1024; n += 2) {
        const float w0 = wp[(size_t)(n + 0) * HG];
        const float w1 = wp[(size_t)(n + 1) * HG];
        const float2 v0 = __half22float2(xp[(size_t)(n + 0) * (DM / 2)]);
        const float2 v1 = __half22float2(xp[(size_t)(n + 1) * (DM / 2)]);
        ax0 = fmaf(v0.x, w0, ax0); ay0 = fmaf(v0.y, w0, ay0);
        ax1 = fmaf(v1.x, w1, ax1); ay1 = fmaf(v1.y, w1, ay1);
        c0 += w0; c1 += w1;
    }

    __shared__ float sg[4][4][64];   // [quarter][g][d]
    __shared__ float sc[4][4];       // [quarter][g]
    sg[qn][g][dp * 2]     = ax0 + ax1;
    sg[qn][g][dp * 2 + 1] = ay0 + ay1;
    if (dp == 0) sc[qn][g] = c0 + c1;
    __syncthreads();

    if (threadIdx.x < 256) {
        const int gg = threadIdx.x >> 6, dd = threadIdx.x & 63;
        float v = (sg[0][gg][dd] + sg[1][gg][dd])
                + (sg[2][gg][dd] + sg[3][gg][dd]);
        if (normalize) {
            const float cs = (sc[0][gg] + sc[1][gg]) + (sc[2][gg] + sc[3][gg]);
            v /= cs;
        }
        __syncthreads();
        sg[0][gg][dd] = v;
    } else {
        __syncthreads();
    }
    __syncthreads();

    if (threadIdx.x < 64) {
        const int dd = threadIdx.x;
        const float v0 = sg[0][0][dd], v1 = sg[0][1][dd];
        const float v2 = sg[0][2][dd], v3 = sg[0][3][dd];
        gmm[(size_t)bh * HD + dd] = __floats2half2_rn(
            fmaxf(fmaxf(v0, v1), fmaxf(v2, v3)),
            fminf(fminf(v0, v1), fminf(v2, v3)));
    }
}

// ---------------------------------------------------------------------------
// prep kernels
// ---------------------------------------------------------------------------
__global__ __launch_bounds__(256) void tofp16(
    const float4* __restrict__ x, __half2* __restrict__ o)
{
    const size_t i = (size_t)blockIdx.x * 256 + threadIdx.x;
    const float4 v = x[i];
    o[2 * i]     = __floats2half2_rn(v.x, v.y);
    o[2 * i + 1] = __floats2half2_rn(v.z, v.w);
}

__global__ __launch_bounds__(256) void wconv4(
    const float* __restrict__ W0, const float* __restrict__ W1,
    const float* __restrict__ W2, const float* __restrict__ W3,
    __half* __restrict__ Tcat, __half* __restrict__ Twt)
{
    __shared__ float tile[32][33];
    const int z = blockIdx.z;
    const float* W = z == 0 ? W0 : z == 1 ? W1 : z == 2 ? W2 : W3;
    __half* Tz = z < 3 ? Tcat + (size_t)z * DM * DM : Twt;
    const int bn = blockIdx.x * 32;
    const int bk = blockIdx.y * 32;
    const int x = threadIdx.x;
    const int y = threadIdx.y;
    #pragma unroll
    for (int i = 0; i < 32; i += 8)
        tile[y + i][x] = W[(size_t)(bk + y + i) * DM + bn + x];
    __syncthreads();
    #pragma unroll
    for (int i = 0; i < 32; i += 8)
        Tz[(size_t)(bn + y + i) * DM + bk + x] =
            __float2half_rn(tile[x][y + i] * WSCALE);
}

__global__ __launch_bounds__(256) void wconv_t(
    const float* __restrict__ W, __half* __restrict__ T, int ncols)
{
    __shared__ float tile[32][33];
    const int bn = blockIdx.x * 32;
    const int bk = blockIdx.y * 32;
    const int x = threadIdx.x;
    const int y = threadIdx.y;
    #pragma unroll
    for (int i = 0; i < 32; i += 8)
        tile[y + i][x] = W[(size_t)(bk + y + i) * ncols + bn + x];
    __syncthreads();
    #pragma unroll
    for (int i = 0; i < 32; i += 8)
        T[(size_t)(bn + y + i) * DM + bk + x] =
            __float2half_rn(tile[x][y + i] * WSCALE);
}

__global__ __launch_bounds__(256) void sgemm_small(
    const float* __restrict__ A, const float* __restrict__ W,
    const float* __restrict__ bias, float* __restrict__ C)
{
    __shared__ __align__(16) float As[16][64];
    __shared__ __align__(16) float Bs[16][64];
    const int tid  = threadIdx.x;
    const int brow = blockIdx.y * 64;
    const int arow = tid >> 2;
    const int akof = (tid & 3) * 4;
    const int bkr  = tid >> 4;
    const int bc4  = (tid & 15) * 4;
    const int trow = (tid >> 4) * 4;
    const int tcol = (tid & 15) * 4;

    float acc[4][4];
    #pragma unroll
    for (int i = 0; i < 4; i++)
        #pragma unroll
        for (int j = 0; j < 4; j++) acc[i][j] = 0.f;

    const float* Ab = A + (size_t)(brow + arow) * DM + akof;
    const float* Wb = W + (size_t)bkr * HG + bc4;

    for (int k0 = 0; k0 < DM; k0 += 16) {
        float4 av = *(const float4*)(Ab + k0);
        As[akof + 0][arow] = av.x;
        As[akof + 1][arow] = av.y;
        As[akof + 2][arow] = av.z;
        As[akof + 3][arow] = av.w;
        float4 bv = *(const float4*)(Wb + (size_t)k0 * HG);
        *(float4*)&Bs[bkr][bc4] = bv;
        __syncthreads();
        #pragma unroll
        for (int kk = 0; kk < 16; kk++) {
            float4 a0 = *(const float4*)&As[kk][trow];
            float4 b0 = *(const float4*)&Bs[kk][tcol];
            float ar[4] = {a0.x, a0.y, a0.z, a0.w};
            float br[4] = {b0.x, b0.y, b0.z, b0.w};
            #pragma unroll
            for (int i = 0; i < 4; i++)
                #pragma unroll
                for (int j = 0; j < 4; j++)
                    acc[i][j] = fmaf(ar[i], br[j], acc[i][j]);
        }
        __syncthreads();
    }
    #pragma unroll
    for (int i = 0; i < 4; i++)
        #pragma unroll
        for (int j = 0; j < 4; j++)
            C[(size_t)(brow + trow + i) * HG + tcol + j] = acc[i][j] + bias[tcol + j];
}

__global__ void bias_comb(const float* __restrict__ bq,
                          const float* __restrict__ Wqa,
                          const float* __restrict__ bqa,
                          float* __restrict__ b1)
{
    __shared__ float part[4][HG];
    const int j = threadIdx.x & 63;
    const int p = threadIdx.x >> 6;
    float s = 0.f;
    for (int i = p * 256; i < (p + 1) * 256; ++i)
        s = fmaf(bq[i], Wqa[(size_t)i * HG + j], s);
    part[p][j] = s;
    __syncthreads();
    if (p == 0)
        b1[j] = bqa[j] + ((part[0][j] + part[1][j]) + (part[2][j] + part[3][j]));
}

// zero the ws1 pad rows (64..127 of the 4th wcat section): 64*1024 halves
__global__ __launch_bounds__(256) void zero_pad(uint4* __restrict__ pad)
{
    pad[blockIdx.x * 256 + threadIdx.x] = make_uint4(0, 0, 0, 0);
}

// ---------------------------------------------------------------------------
// Launch
// ---------------------------------------------------------------------------
extern "C" void kernel_launch(void* const* d_in, const int* in_sizes, int n_in,
                              void* d_out, int out_size)
{
    const float* hs   = (const float*)d_in[0];
    const float* mask = (const float*)d_in[1];
    const float* Wq   = (const float*)d_in[2];
    const float* bq   = (const float*)d_in[3];
    const float* Wqa  = (const float*)d_in[4];
    const float* bqa  = (const float*)d_in[5];
    const float* Wk   = (const float*)d_in[6];
    const float* bk   = (const float*)d_in[7];
    const float* Wka  = (const float*)d_in[8];
    const float* bka  = (const float*)d_in[9];
    const float* Wv   = (const float*)d_in[10];
    const float* bv   = (const float*)d_in[11];
    const float* Wt   = (const float*)d_in[12];
    const float* bt   = (const float*)d_in[13];
    float* out = (float*)d_out;

    float *s1, *s2, *b1, *zv;
    __half2 *gmm1, *gmm2;
    __half *qh, *kh, *vh, *ah, *wcat, *wt, *ws2;
    cudaGetSymbolAddress((void**)&s1,   g_s1);
    cudaGetSymbolAddress((void**)&s2,   g_s2);
    cudaGetSymbolAddress((void**)&b1,   g_b1);
    cudaGetSymbolAddress((void**)&zv,   g_zero);
    cudaGetSymbolAddress((void**)&gmm1, g_gmm1);
    cudaGetSymbolAddress((void**)&gmm2, g_gmm2);
    cudaGetSymbolAddress((void**)&qh,   g_qh);
    cudaGetSymbolAddress((void**)&kh,   g_kh);
    cudaGetSymbolAddress((void**)&vh,   g_vh);
    cudaGetSymbolAddress((void**)&ah,   g_ah);
    cudaGetSymbolAddress((void**)&wcat, g_wcat);
    cudaGetSymbolAddress((void**)&wt,   g_wt);
    cudaGetSymbolAddress((void**)&ws2,  g_ws2);

    cudaFuncSetAttribute(gemm_qkvs,   cudaFuncAttributeMaxDynamicSharedMemorySize, SMEM_BIG);
    cudaFuncSetAttribute(gemm_hmma_f, cudaFuncAttributeMaxDynamicSharedMemorySize, SMEM_BIGF);
    cudaFuncSetAttribute(gemm_n64_f,  cudaFuncAttributeMaxDynamicSharedMemorySize, SMEM_N64F);

    const size_t WSZ = (size_t)DM * DM;
    __half* ws1 = wcat + 3 * WSZ;
    uint4* pad = (uint4*)(wcat + 3 * WSZ + 64 * DM);   // 64 rows x 1024 halves

    dim3 bW(32, 8);

    // --- prep ---
    zero_pad<<<(64 * DM / 8) / 256, 256>>>(pad);
    wconv4<<<dim3(DM / 32, DM / 32, 4), bW>>>(Wq, Wk, Wv, Wt, wcat, wt);
    sgemm_small<<<dim3(1, DM / 64), 256>>>(Wq, Wqa, zv, s2);
    wconv_t<<<dim3(HG / 32, DM / 32), bW>>>(s2, ws1, HG);
    bias_comb<<<1, 256>>>(bq, Wqa, bqa, b1);
    wconv_t<<<dim3(HG / 32, DM / 32), bW>>>(Wka, ws2, HG);
    tofp16<<<(MROWS * DM / 4) / 256, 256>>>((const float4*)hs, (__half2*)ah);

    // --- fused q,k,v,s1 projection ---
    gemm_qkvs<<<dim3(25, MROWS / 128), 256, SMEM_BIG>>>(
        ah, wcat, bq, bk, bv, b1, mask, qh, kh, vh, s1);

    // --- q-attention reduction (fused gsum+colsum+minmax) ---
    gsum_fused<<<BATCH * NH, 512>>>(qh, s1, 1, gmm1);

    // --- ksc (fused qk from kh+gmm1) -> k-side reduction ---
    gemm_n64_f<<<MROWS / 128, 256, SMEM_N64F>>>(kh, gmm1, ws2, bka, mask, s2);
    gsum_fused<<<BATCH * NH, 512>>>(kh, s2, 0, gmm2);

    // --- out = (fused u from vh+gmm2) @ Wt + bt + qh ---
    gemm_hmma_f<<<dim3(DM / 128, MROWS / 128), 256, SMEM_BIGF>>>(
        vh, gmm2, wt, bt, qh, out);
}

// round 13
// speedup vs baseline: 1.1040x; 1.0959x over previous
#include <cuda_runtime.h>
#include <cuda_fp16.h>
#include <cstdint>

// Problem constants
#define BATCH 8
#define SEQ   4096
#define DM    1024
#define NH    16
#define NG    4
#define HD    64
#define HG    (NH*NG)          // 64
#define MROWS (BATCH*SEQ)      // 32768
#define INV_SCALE 0.125f       // 1/sqrt(64)
#define WSCALE 1024.0f
#define WUNSCALE (1.0f/1024.0f)
#define GSZ (BATCH*NH*HD*NG)   // 32768

// ---------------------------------------------------------------------------
// Scratch (device globals)
// ---------------------------------------------------------------------------
__device__ float g_s1[MROWS * HG];              // exp(q-scores)
__device__ float g_s2[MROWS * HG];              // ksc; WqWqa fp32 tmp during prep
__device__ __align__(16) float g_gq[GSZ];
__device__ __align__(16) float g_gk[GSZ];
__device__ __align__(16) float g_cs[BATCH * HG];// col sums of exp
__device__ float g_b1[HG];                      // bq@Wqa + bqa
__device__ float g_zero[HG];
__device__ __align__(256) __half2 g_gmm1[BATCH * NH * HD];  // (gmax,gmin) of gq/cs
__device__ __align__(256) __half2 g_gmm2[BATCH * NH * HD];  // (gmax,gmin) of gk
__device__ __align__(256) __half g_qh[MROWS * DM];
__device__ __align__(256) __half g_kh[MROWS * DM];
__device__ __align__(256) __half g_vh[MROWS * DM];
__device__ __align__(256) __half g_ah[MROWS * DM];            // hs fp16
__device__ __align__(256) __half g_wcat[(3 * DM + 128) * DM]; // WqT|WkT|WvT|ws1pad
__device__ __align__(256) __half g_wt[DM * DM];               // WtT
__device__ __align__(256) __half g_ws2[HG * DM];              // WkaT

// ---------------------------------------------------------------------------
// PTX helpers (plain sm_103-safe)
// ---------------------------------------------------------------------------
__device__ __forceinline__ uint32_t smem_u32(const void* p) {
    uint32_t a;
    asm("{ .reg .u64 t; cvta.to.shared.u64 t, %1; cvt.u32.u64 %0, t; }"
        : "=r"(a) : "l"(p));
    return a;
}
#define CP_ASYNC16(s, g) \
    asm volatile("cp.async.cg.shared.global [%0], [%1], 16;" :: "r"(s), "l"(g))
#define CP_COMMIT() asm volatile("cp.async.commit_group;" ::: "memory")
#define CP_WAIT(n)  asm volatile("cp.async.wait_group %0;" :: "n"(n) : "memory")
#define LDMX4(r, addr) \
    asm volatile("ldmatrix.sync.aligned.m8n8.x4.shared.b16 {%0,%1,%2,%3}, [%4];" \
        : "=r"((r)[0]), "=r"((r)[1]), "=r"((r)[2]), "=r"((r)[3]) : "r"(addr))
#define MMA_F16(d, a, b0, b1) \
    asm volatile("mma.sync.aligned.m16n8k16.row.col.f32.f16.f16.f32 " \
        "{%0,%1,%2,%3}, {%4,%5,%6,%7}, {%8,%9}, {%0,%1,%2,%3};" \
        : "+f"((d)[0]), "+f"((d)[1]), "+f"((d)[2]), "+f"((d)[3]) \
        : "r"((a)[0]), "r"((a)[1]), "r"((a)[2]), "r"((a)[3]), "r"(b0), "r"(b1))

#define SWZ(o) ((uint32_t)(o) ^ ((((uint32_t)(o)) >> 3) & 0x70))

#define BK 64
#define STG_BIG 32768
#define SMEM_BIG (2 * STG_BIG)

// Apply max-trick to one uint4 (8 fp16) with 8 gmm half2 entries (m0,m1).
__device__ __forceinline__ uint4 maxg_apply(uint4 xv, uint4 m0, uint4 m1) {
    uint32_t out[4];
    const uint32_t* xw  = (const uint32_t*)&xv;
    const uint32_t* mw0 = (const uint32_t*)&m0;
    const uint32_t* mw1 = (const uint32_t*)&m1;
    #pragma unroll
    for (int j = 0; j < 4; ++j) {
        const uint32_t ga = (j < 2) ? mw0[2 * j]     : mw1[2 * j - 4];
        const uint32_t gb = (j < 2) ? mw0[2 * j + 1] : mw1[2 * j - 3];
        const __half2 x2 = *(const __half2*)&xw[j];
        const __half2 g0 = *(const __half2*)&ga;   // (gmax_d, gmin_d)
        const __half2 g1 = *(const __half2*)&gb;
        const float x0 = __low2float(x2), x1 = __high2float(x2);
        const float s0 = (x0 >= 0.f) ? __low2float(g0) : __high2float(g0);
        const float s1 = (x1 >= 0.f) ? __low2float(g1) : __high2float(g1);
        const __half2 r = __floats2half2_rn(x0 * s0, x1 * s1);
        out[j] = *(const uint32_t*)&r;
    }
    return *(const uint4*)out;
}

// ---------------------------------------------------------------------------
// Fused QKV+S1 GEMM.
// ---------------------------------------------------------------------------
__global__ __launch_bounds__(256, 2) void gemm_qkvs(
    const __half* __restrict__ A, const __half* __restrict__ B,
    const float* __restrict__ bq, const float* __restrict__ bk,
    const float* __restrict__ bv, const float* __restrict__ b1,
    const float* __restrict__ mask,
    __half* __restrict__ Q, __half* __restrict__ K, __half* __restrict__ V,
    float* __restrict__ S1)
{
    extern __shared__ char smem[];
    const uint32_t sbase = smem_u32(smem);
    const int tid  = threadIdx.x;
    const int lane = tid & 31;
    const int wid  = tid >> 5;
    const int wm   = wid & 3;
    const int wn   = wid >> 2;
    const int brow = blockIdx.y * 128;
    const int bcol = blockIdx.x * 128;
    const int which = blockIdx.x >> 3;
    const int bcl   = bcol & (DM - 1);
    const float* bias = which == 0 ? bq : which == 1 ? bk : which == 2 ? bv : b1;

    const int lrow  = tid >> 1;
    const int lhalf = tid & 1;
    const __half* gA = A + (size_t)(brow + lrow) * DM + lhalf * 32;
    const __half* gB = B + (size_t)(bcol + lrow) * DM + lhalf * 32;
    uint32_t soff[4];
    #pragma unroll
    for (int i = 0; i < 4; ++i)
        soff[i] = SWZ(lrow * 128 + lhalf * 64 + i * 16);

    float acc[2][8][4];
    #pragma unroll
    for (int mi = 0; mi < 2; ++mi)
        #pragma unroll
        for (int nt = 0; nt < 8; ++nt)
            #pragma unroll
            for (int r = 0; r < 4; ++r) acc[mi][nt][r] = 0.f;

    const int frow = lane & 15;
    const int fcol = (lane >> 4) << 4;

    {
        #pragma unroll
        for (int i = 0; i < 4; ++i) {
            CP_ASYNC16(sbase +         soff[i], gA + i * 8);
            CP_ASYNC16(sbase + 16384 + soff[i], gB + i * 8);
        }
        CP_COMMIT();
    }

    #pragma unroll 1
    for (int c = 0; c < 16; ++c) {
        const int s = c & 1;
        if (c + 1 < 16) {
            const uint32_t sb = sbase + ((c + 1) & 1) * STG_BIG;
            const size_t ko = (size_t)(c + 1) * BK;
            #pragma unroll
            for (int i = 0; i < 4; ++i) {
                CP_ASYNC16(sb +         soff[i], gA + ko + i * 8);
                CP_ASYNC16(sb + 16384 + soff[i], gB + ko + i * 8);
            }
            CP_COMMIT();
            CP_WAIT(1);
        } else {
            CP_WAIT(0);
        }
        __syncthreads();

        const uint32_t stg = sbase + s * STG_BIG;
        #pragma unroll
        for (int ks = 0; ks < 4; ++ks) {
            const uint32_t kb = ks * 32 + fcol;
            uint32_t a_r[2][4];
            #pragma unroll
            for (int mi = 0; mi < 2; ++mi) {
                const uint32_t o = SWZ((wm * 32 + mi * 16 + frow) * 128 + kb);
                LDMX4(a_r[mi], stg + o);
            }
            uint32_t b_r[4][4];
            #pragma unroll
            for (int nt2 = 0; nt2 < 4; ++nt2) {
                const uint32_t o = SWZ((wn * 64 + nt2 * 16 + frow) * 128 + kb);
                LDMX4(b_r[nt2], stg + 16384 + o);
            }
            #pragma unroll
            for (int mi = 0; mi < 2; ++mi)
                #pragma unroll
                for (int nt = 0; nt < 8; ++nt)
                    MMA_F16(acc[mi][nt], a_r[mi], b_r[nt >> 1][nt & 1], b_r[nt >> 1][(nt & 1) + 2]);
        }
        __syncthreads();
    }

    const int er = brow + wm * 32 + (lane >> 2);
    const int ec = bcl + wn * 64 + (lane & 3) * 2;
    if (which < 3) {
        __half* Ch = which == 0 ? Q : which == 1 ? K : V;
        #pragma unroll
        for (int mi = 0; mi < 2; ++mi) {
            #pragma unroll
            for (int nt = 0; nt < 8; ++nt) {
                const int row = er + mi * 16;
                const int col = ec + nt * 8;
                const float b0 = bias[col], b1v = bias[col + 1];
                *(__half2*)(Ch + (size_t)row * DM + col) =
                    __floats2half2_rn(acc[mi][nt][0] * WUNSCALE + b0,
                                      acc[mi][nt][1] * WUNSCALE + b1v);
                *(__half2*)(Ch + (size_t)(row + 8) * DM + col) =
                    __floats2half2_rn(acc[mi][nt][2] * WUNSCALE + b0,
                                      acc[mi][nt][3] * WUNSCALE + b1v);
            }
        }
    } else if (wn == 0) {
        #pragma unroll
        for (int mi = 0; mi < 2; ++mi) {
            #pragma unroll
            for (int nt = 0; nt < 8; ++nt) {
                const int row = er + mi * 16;
                const int col = (nt * 8 + (lane & 3) * 2);
                const float b0 = bias[col], b1v = bias[col + 1];
                const float m0 = mask[row], m1 = mask[row + 8];
                S1[(size_t)row * HG + col] =
                    __expf((acc[mi][nt][0] * WUNSCALE + b0) * INV_SCALE + m0);
                S1[(size_t)row * HG + col + 1] =
                    __expf((acc[mi][nt][1] * WUNSCALE + b1v) * INV_SCALE + m0);
                S1[(size_t)(row + 8) * HG + col] =
                    __expf((acc[mi][nt][2] * WUNSCALE + b0) * INV_SCALE + m1);
                S1[(size_t)(row + 8) * HG + col + 1] =
                    __expf((acc[mi][nt][3] * WUNSCALE + b1v) * INV_SCALE + m1);
            }
        }
    }
}

// ---------------------------------------------------------------------------
// Final GEMM, fused u: X staged via cp.async, converted IN PLACE.
// out = (vh*sel(gmm2)) @ WtT + bt + qh
// ---------------------------------------------------------------------------
#define GMM_OFF (2 * STG_BIG)
#define SMEM_BIGF (2 * STG_BIG + 4096)

__global__ __launch_bounds__(256, 2) void gemm_hmma_f(
    const __half* __restrict__ X, const __half2* __restrict__ gmm,
    const __half* __restrict__ B,
    const float* __restrict__ bias, const __half* __restrict__ addv,
    float* __restrict__ C)
{
    extern __shared__ char smem[];
    const uint32_t sbase = smem_u32(smem);
    const int tid  = threadIdx.x;
    const int lane = tid & 31;
    const int wid  = tid >> 5;
    const int wm   = wid & 3;
    const int wn   = wid >> 2;
    const int brow = blockIdx.y * 128;
    const int bcol = blockIdx.x * 128;
    const int bb   = brow >> 12;

    const int lrow  = tid >> 1;
    const int lhalf = tid & 1;
    const __half* gX = X + (size_t)(brow + lrow) * DM + lhalf * 32;
    const __half* gB = B + (size_t)(bcol + lrow) * DM + lhalf * 32;
    uint32_t soff[4];
    #pragma unroll
    for (int i = 0; i < 4; ++i)
        soff[i] = SWZ(lrow * 128 + lhalf * 64 + i * 16);

    *(uint4*)(smem + GMM_OFF + tid * 16) =
        ((const uint4*)(gmm + (size_t)bb * NH * HD))[tid];

    {
        #pragma unroll
        for (int i = 0; i < 4; ++i) {
            CP_ASYNC16(sbase +         soff[i], gX + i * 8);
            CP_ASYNC16(sbase + 16384 + soff[i], gB + i * 8);
        }
        CP_COMMIT();
    }
    __syncthreads();   // gmm visible

    float acc[2][8][4];
    #pragma unroll
    for (int mi = 0; mi < 2; ++mi)
        #pragma unroll
        for (int nt = 0; nt < 8; ++nt)
            #pragma unroll
            for (int r = 0; r < 4; ++r) acc[mi][nt][r] = 0.f;

    const int frow = lane & 15;
    const int fcol = (lane >> 4) << 4;
    const uint32_t gmo = GMM_OFF + lhalf * 128;

    #pragma unroll 1
    for (int c = 0; c < 16; ++c) {
        const int s = c & 1;
        if (c + 1 < 16) {
            const uint32_t sb = sbase + ((c + 1) & 1) * STG_BIG;
            const size_t ko = (size_t)(c + 1) * BK;
            #pragma unroll
            for (int i = 0; i < 4; ++i) {
                CP_ASYNC16(sb +         soff[i], gX + ko + i * 8);
                CP_ASYNC16(sb + 16384 + soff[i], gB + ko + i * 8);
            }
            CP_COMMIT();
            CP_WAIT(1);
        } else {
            CP_WAIT(0);
        }

        {
            const uint32_t go = gmo + c * 256;
            char* sA = smem + s * STG_BIG;
            #pragma unroll
            for (int i = 0; i < 4; ++i) {
                const uint4 xv = *(const uint4*)(sA + soff[i]);
                const uint4 m0 = *(const uint4*)(smem + go + i * 32);
                const uint4 m1 = *(const uint4*)(smem + go + i * 32 + 16);
                *(uint4*)(sA + soff[i]) = maxg_apply(xv, m0, m1);
            }
        }
        __syncthreads();

        const uint32_t stg = sbase + s * STG_BIG;
        #pragma unroll
        for (int ks = 0; ks < 4; ++ks) {
            const uint32_t kb = ks * 32 + fcol;
            uint32_t a_r[2][4];
            #pragma unroll
            for (int mi = 0; mi < 2; ++mi) {
                const uint32_t o = SWZ((wm * 32 + mi * 16 + frow) * 128 + kb);
                LDMX4(a_r[mi], stg + o);
            }
            uint32_t b_r[4][4];
            #pragma unroll
            for (int nt2 = 0; nt2 < 4; ++nt2) {
                const uint32_t o = SWZ((wn * 64 + nt2 * 16 + frow) * 128 + kb);
                LDMX4(b_r[nt2], stg + 16384 + o);
            }
            #pragma unroll
            for (int mi = 0; mi < 2; ++mi)
                #pragma unroll
                for (int nt = 0; nt < 8; ++nt)
                    MMA_F16(acc[mi][nt], a_r[mi], b_r[nt >> 1][nt & 1], b_r[nt >> 1][(nt & 1) + 2]);
        }
        __syncthreads();
    }

    const int er = brow + wm * 32 + (lane >> 2);
    const int ec = bcol + wn * 64 + (lane & 3) * 2;
    #pragma unroll
    for (int mi = 0; mi < 2; ++mi) {
        #pragma unroll
        for (int nt = 0; nt < 8; ++nt) {
            const int row = er + mi * 16;
            const int col = ec + nt * 8;
            const float b0 = bias[col], b1v = bias[col + 1];
            const float2 f0 = __half22float2(*(const __half2*)(addv + (size_t)row * DM + col));
            const float2 f1 = __half22float2(*(const __half2*)(addv + (size_t)(row + 8) * DM + col));
            *(float2*)(C + (size_t)row * DM + col) = make_float2(
                acc[mi][nt][0] * WUNSCALE + b0 + f0.x,
                acc[mi][nt][1] * WUNSCALE + b1v + f0.y);
            *(float2*)(C + (size_t)(row + 8) * DM + col) = make_float2(
                acc[mi][nt][2] * WUNSCALE + b0 + f1.x,
                acc[mi][nt][3] * WUNSCALE + b1v + f1.y);
        }
    }
}

// ---------------------------------------------------------------------------
// N=64 GEMM, fused qk: async X + in-place convert; ksc epilogue.
// ---------------------------------------------------------------------------
#define STG_N64 24576
#define GMM_OFF64 (2 * STG_N64)
#define SMEM_N64F (2 * STG_N64 + 4096)

__global__ __launch_bounds__(256, 2) void gemm_n64_f(
    const __half* __restrict__ X, const __half2* __restrict__ gmm,
    const __half* __restrict__ B,
    const float* __restrict__ bias, const float* __restrict__ mask,
    float* __restrict__ C)
{
    extern __shared__ char smem[];
    const uint32_t sbase = smem_u32(smem);
    const int tid  = threadIdx.x;
    const int lane = tid & 31;
    const int wid  = tid >> 5;
    const int wm   = wid & 3;
    const int wn   = wid >> 2;
    const int brow = blockIdx.x * 128;
    const int bb   = brow >> 12;

    const int lrow  = tid >> 1;
    const int lhalf = tid & 1;
    const __half* gX = X + (size_t)(brow + lrow) * DM + lhalf * 32;
    uint32_t aoff[4];
    #pragma unroll
    for (int i = 0; i < 4; ++i)
        aoff[i] = SWZ(lrow * 128 + lhalf * 64 + i * 16);
    const int  brw   = (tid & 127) >> 1;
    const int  bhalf = tid & 1;
    const bool bldr  = tid < 128;
    const __half* gB = B + (size_t)brw * DM + bhalf * 32;
    uint32_t boff[4];
    #pragma unroll
    for (int i = 0; i < 4; ++i)
        boff[i] = SWZ(brw * 128 + bhalf * 64 + i * 16);

    *(uint4*)(smem + GMM_OFF64 + tid * 16) =
        ((const uint4*)(gmm + (size_t)bb * NH * HD))[tid];

    {
        #pragma unroll
        for (int i = 0; i < 4; ++i) {
            CP_ASYNC16(sbase + aoff[i], gX + i * 8);
            if (bldr) CP_ASYNC16(sbase + 16384 + boff[i], gB + i * 8);
        }
        CP_COMMIT();
    }
    __syncthreads();

    float acc[2][4][4];
    #pragma unroll
    for (int mi = 0; mi < 2; ++mi)
        #pragma unroll
        for (int nt = 0; nt < 4; ++nt)
            #pragma unroll
            for (int r = 0; r < 4; ++r) acc[mi][nt][r] = 0.f;

    const int frow = lane & 15;
    const int fcol = (lane >> 4) << 4;
    const uint32_t gmo = GMM_OFF64 + lhalf * 128;

    #pragma unroll 1
    for (int c = 0; c < 16; ++c) {
        const int s = c & 1;
        if (c + 1 < 16) {
            const uint32_t sb = sbase + ((c + 1) & 1) * STG_N64;
            const size_t ko = (size_t)(c + 1) * BK;
            #pragma unroll
            for (int i = 0; i < 4; ++i) {
                CP_ASYNC16(sb + aoff[i], gX + ko + i * 8);
                if (bldr) CP_ASYNC16(sb + 16384 + boff[i], gB + ko + i * 8);
            }
            CP_COMMIT();
            CP_WAIT(1);
        } else {
            CP_WAIT(0);
        }

        {
            const uint32_t go = gmo + c * 256;
            char* sA = smem + s * STG_N64;
            #pragma unroll
            for (int i = 0; i < 4; ++i) {
                const uint4 xv = *(const uint4*)(sA + aoff[i]);
                const uint4 m0 = *(const uint4*)(smem + go + i * 32);
                const uint4 m1 = *(const uint4*)(smem + go + i * 32 + 16);
                *(uint4*)(sA + aoff[i]) = maxg_apply(xv, m0, m1);
            }
        }
        __syncthreads();

        const uint32_t stg = sbase + s * STG_N64;
        #pragma unroll
        for (int ks = 0; ks < 4; ++ks) {
            const uint32_t kb = ks * 32 + fcol;
            uint32_t a_r[2][4];
            #pragma unroll
            for (int mi = 0; mi < 2; ++mi) {
                const uint32_t o = SWZ((wm * 32 + mi * 16 + frow) * 128 + kb);
                LDMX4(a_r[mi], stg + o);
            }
            uint32_t b_r[2][4];
            #pragma unroll
            for (int nt2 = 0; nt2 < 2; ++nt2) {
                const uint32_t o = SWZ((wn * 32 + nt2 * 16 + frow) * 128 + kb);
                LDMX4(b_r[nt2], stg + 16384 + o);
            }
            #pragma unroll
            for (int mi = 0; mi < 2; ++mi)
                #pragma unroll
                for (int nt = 0; nt < 4; ++nt)
                    MMA_F16(acc[mi][nt], a_r[mi], b_r[nt >> 1][nt & 1], b_r[nt >> 1][(nt & 1) + 2]);
        }
        __syncthreads();
    }

    const int er = brow + wm * 32 + (lane >> 2);
    const int ec = wn * 32 + (lane & 3) * 2;
    #pragma unroll
    for (int mi = 0; mi < 2; ++mi) {
        #pragma unroll
        for (int nt = 0; nt < 4; ++nt) {
            const int row = er + mi * 16;
            const int col = ec + nt * 8;
            const float b0 = bias[col], b1v = bias[col + 1];
            const float m0 = mask[row], m1 = mask[row + 8];
            *(float2*)(C + (size_t)row * HG + col) = make_float2(
                (acc[mi][nt][0] * WUNSCALE + b0) * INV_SCALE + m0,
                (acc[mi][nt][1] * WUNSCALE + b1v) * INV_SCALE + m0);
            *(float2*)(C + (size_t)(row + 8) * HG + col) = make_float2(
                (acc[mi][nt][2] * WUNSCALE + b0) * INV_SCALE + m1,
                (acc[mi][nt][3] * WUNSCALE + b1v) * INV_SCALE + m1);
        }
    }
}

// ---------------------------------------------------------------------------
// gminmax: gmm[b,h,d] = (max_g, min_g) of g[b,h,d,g] (optionally / cs)
// ---------------------------------------------------------------------------
__global__ __launch_bounds__(256) void gminmax(
    const float* __restrict__ g, const float* __restrict__ cs,
    __half2* __restrict__ gmm)
{
    const int i = blockIdx.x * 256 + threadIdx.x;   // (b*16+h)*64+d
    float4 v = ((const float4*)g)[i];
    if (cs) {
        const float4 c4 = ((const float4*)cs)[i >> 6];
        v.x /= c4.x; v.y /= c4.y; v.z /= c4.z; v.w /= c4.w;
    }
    const float mx = fmaxf(fmaxf(v.x, v.y), fmaxf(v.z, v.w));
    const float mn = fminf(fminf(v.x, v.y), fminf(v.z, v.w));
    gmm[i] = __floats2half2_rn(mx, mn);
}

// ---------------------------------------------------------------------------
// prep kernels
// ---------------------------------------------------------------------------
__global__ __launch_bounds__(256) void tofp16(
    const float4* __restrict__ x, __half2* __restrict__ o)
{
    const size_t i = (size_t)blockIdx.x * 256 + threadIdx.x;
    const float4 v = x[i];
    o[2 * i]     = __floats2half2_rn(v.x, v.y);
    o[2 * i + 1] = __floats2half2_rn(v.z, v.w);
}

__global__ __launch_bounds__(256) void wconv4(
    const float* __restrict__ W0, const float* __restrict__ W1,
    const float* __restrict__ W2, const float* __restrict__ W3,
    __half* __restrict__ Tcat, __half* __restrict__ Twt)
{
    __shared__ float tile[32][33];
    const int z = blockIdx.z;
    const float* W = z == 0 ? W0 : z == 1 ? W1 : z == 2 ? W2 : W3;
    __half* Tz = z < 3 ? Tcat + (size_t)z * DM * DM : Twt;
    const int bn = blockIdx.x * 32;
    const int bk = blockIdx.y * 32;
    const int x = threadIdx.x;
    const int y = threadIdx.y;
    #pragma unroll
    for (int i = 0; i < 32; i += 8)
        tile[y + i][x] = W[(size_t)(bk + y + i) * DM + bn + x];
    __syncthreads();
    #pragma unroll
    for (int i = 0; i < 32; i += 8)
        Tz[(size_t)(bn + y + i) * DM + bk + x] =
            __float2half_rn(tile[x][y + i] * WSCALE);
}

__global__ __launch_bounds__(256) void wconv_t(
    const float* __restrict__ W, __half* __restrict__ T, int ncols)
{
    __shared__ float tile[32][33];
    const int bn = blockIdx.x * 32;
    const int bk = blockIdx.y * 32;
    const int x = threadIdx.x;
    const int y = threadIdx.y;
    #pragma unroll
    for (int i = 0; i < 32; i += 8)
        tile[y + i][x] = W[(size_t)(bk + y + i) * ncols + bn + x];
    __syncthreads();
    #pragma unroll
    for (int i = 0; i < 32; i += 8)
        T[(size_t)(bn + y + i) * DM + bk + x] =
            __float2half_rn(tile[x][y + i] * WSCALE);
}

__global__ __launch_bounds__(256) void sgemm_small(
    const float* __restrict__ A, const float* __restrict__ W,
    const float* __restrict__ bias, float* __restrict__ C)
{
    __shared__ __align__(16) float As[16][64];
    __shared__ __align__(16) float Bs[16][64];
    const int tid  = threadIdx.x;
    const int brow = blockIdx.y * 64;
    const int arow = tid >> 2;
    const int akof = (tid & 3) * 4;
    const int bkr  = tid >> 4;
    const int bc4  = (tid & 15) * 4;
    const int trow = (tid >> 4) * 4;
    const int tcol = (tid & 15) * 4;

    float acc[4][4];
    #pragma unroll
    for (int i = 0; i < 4; i++)
        #pragma unroll
        for (int j = 0; j < 4; j++) acc[i][j] = 0.f;

    const float* Ab = A + (size_t)(brow + arow) * DM + akof;
    const float* Wb = W + (size_t)bkr * HG + bc4;

    for (int k0 = 0; k0 < DM; k0 += 16) {
        float4 av = *(const float4*)(Ab + k0);
        As[akof + 0][arow] = av.x;
        As[akof + 1][arow] = av.y;
        As[akof + 2][arow] = av.z;
        As[akof + 3][arow] = av.w;
        float4 bv = *(const float4*)(Wb + (size_t)k0 * HG);
        *(float4*)&Bs[bkr][bc4] = bv;
        __syncthreads();
        #pragma unroll
        for (int kk = 0; kk < 16; kk++) {
            float4 a0 = *(const float4*)&As[kk][trow];
            float4 b0 = *(const float4*)&Bs[kk][tcol];
            float ar[4] = {a0.x, a0.y, a0.z, a0.w};
            float br[4] = {b0.x, b0.y, b0.z, b0.w};
            #pragma unroll
            for (int i = 0; i < 4; i++)
                #pragma unroll
                for (int j = 0; j < 4; j++)
                    acc[i][j] = fmaf(ar[i], br[j], acc[i][j]);
        }
        __syncthreads();
    }
    #pragma unroll
    for (int i = 0; i < 4; i++)
        #pragma unroll
        for (int j = 0; j < 4; j++)
            C[(size_t)(brow + trow + i) * HG + tcol + j] = acc[i][j] + bias[tcol + j];
}

__global__ void bias_comb(const float* __restrict__ bq,
                          const float* __restrict__ Wqa,
                          const float* __restrict__ bqa,
                          float* __restrict__ b1)
{
    __shared__ float part[4][HG];
    const int j = threadIdx.x & 63;
    const int p = threadIdx.x >> 6;
    float s = 0.f;
    for (int i = p * 256; i < (p + 1) * 256; ++i)
        s = fmaf(bq[i], Wqa[(size_t)i * HG + j], s);
    part[p][j] = s;
    __syncthreads();
    if (p == 0)
        b1[j] = bqa[j] + ((part[0][j] + part[1][j]) + (part[2][j] + part[3][j]));
}

// zero gq, gk, colsum, ws1 pad rows
__global__ __launch_bounds__(256) void zero_misc(
    float* __restrict__ gq, float* __restrict__ gk,
    float* __restrict__ cs, uint32_t* __restrict__ pad)
{
    const int i = blockIdx.x * 256 + threadIdx.x;   // 0..32767
    gq[i] = 0.f; gk[i] = 0.f; pad[i] = 0u;
    if (i < BATCH * HG) cs[i] = 0.f;
}

// per-(b,col) sum of exp over n (coalesced)
__global__ __launch_bounds__(256) void sum_cols(
    const float* __restrict__ s, float* __restrict__ cs)
{
    const int b  = blockIdx.x;
    const int n0 = blockIdx.y * 256;
    const int c  = threadIdx.x & 63;
    const int rq = threadIdx.x >> 6;
    const float* base = s + ((size_t)b * SEQ + n0) * HG;
    float acc = 0.f;
    for (int n = rq; n < 256; n += 4)
        acc += base[(size_t)n * HG + c];
    __shared__ float part[4][HG];
    part[rq][c] = acc;
    __syncthreads();
    if (rq == 0)
        atomicAdd(&cs[b * HG + c],
                  (part[0][c] + part[1][c]) + (part[2][c] + part[3][c]));
}

__global__ __launch_bounds__(256) void gsum_h(
    const __half* __restrict__ x, const float* __restrict__ w,
    float* __restrict__ out)
{
    const int b = blockIdx.x / NH;
    const int h = blockIdx.x % NH;
    const int n0 = blockIdx.y * 256;
    const int g = threadIdx.x >> 6;
    const int d = threadIdx.x & 63;
    const __half* xp = x + ((size_t)b * SEQ + n0) * DM + h * HD + d;
    const float* wp = w + ((size_t)b * SEQ + n0) * HG + h * NG + g;
    float a0 = 0.f, a1 = 0.f, a2 = 0.f, a3 = 0.f;
    #pragma unroll 4
    for (int n = 0; n < 256; n += 4) {
        a0 = fmaf(__half2float(xp[(size_t)(n + 0) * DM]), wp[(size_t)(n + 0) * HG], a0);
        a1 = fmaf(__half2float(xp[(size_t)(n + 1) * DM]), wp[(size_t)(n + 1) * HG], a1);
        a2 = fmaf(__half2float(xp[(size_t)(n + 2) * DM]), wp[(size_t)(n + 2) * HG], a2);
        a3 = fmaf(__half2float(xp[(size_t)(n + 3) * DM]), wp[(size_t)(n + 3) * HG], a3);
    }
    atomicAdd(&out[(((size_t)(b * NH + h) * HD) + d) * NG + g],
              (a0 + a1) + (a2 + a3));
}

// ---------------------------------------------------------------------------
// Launch
// ---------------------------------------------------------------------------
extern "C" void kernel_launch(void* const* d_in, const int* in_sizes, int n_in,
                              void* d_out, int out_size)
{
    const float* hs   = (const float*)d_in[0];
    const float* mask = (const float*)d_in[1];
    const float* Wq   = (const float*)d_in[2];
    const float* bq   = (const float*)d_in[3];
    const float* Wqa  = (const float*)d_in[4];
    const float* bqa  = (const float*)d_in[5];
    const float* Wk   = (const float*)d_in[6];
    const float* bk   = (const float*)d_in[7];
    const float* Wka  = (const float*)d_in[8];
    const float* bka  = (const float*)d_in[9];
    const float* Wv   = (const float*)d_in[10];
    const float* bv   = (const float*)d_in[11];
    const float* Wt   = (const float*)d_in[12];
    const float* bt   = (const float*)d_in[13];
    float* out = (float*)d_out;

    float *s1, *s2, *gq, *gk, *cs, *b1, *zv;
    __half2 *gmm1, *gmm2;
    __half *qh, *kh, *vh, *ah, *wcat, *wt, *ws2;
    cudaGetSymbolAddress((void**)&s1,   g_s1);
    cudaGetSymbolAddress((void**)&s2,   g_s2);
    cudaGetSymbolAddress((void**)&gq,   g_gq);
    cudaGetSymbolAddress((void**)&gk,   g_gk);
    cudaGetSymbolAddress((void**)&cs,   g_cs);
    cudaGetSymbolAddress((void**)&b1,   g_b1);
    cudaGetSymbolAddress((void**)&zv,   g_zero);
    cudaGetSymbolAddress((void**)&gmm1, g_gmm1);
    cudaGetSymbolAddress((void**)&gmm2, g_gmm2);
    cudaGetSymbolAddress((void**)&qh,   g_qh);
    cudaGetSymbolAddress((void**)&kh,   g_kh);
    cudaGetSymbolAddress((void**)&vh,   g_vh);
    cudaGetSymbolAddress((void**)&ah,   g_ah);
    cudaGetSymbolAddress((void**)&wcat, g_wcat);
    cudaGetSymbolAddress((void**)&wt,   g_wt);
    cudaGetSymbolAddress((void**)&ws2,  g_ws2);

    cudaFuncSetAttribute(gemm_qkvs,   cudaFuncAttributeMaxDynamicSharedMemorySize, SMEM_BIG);
    cudaFuncSetAttribute(gemm_hmma_f, cudaFuncAttributeMaxDynamicSharedMemorySize, SMEM_BIGF);
    cudaFuncSetAttribute(gemm_n64_f,  cudaFuncAttributeMaxDynamicSharedMemorySize, SMEM_N64F);

    const size_t WSZ = (size_t)DM * DM;
    __half* ws1 = wcat + 3 * WSZ;
    uint32_t* pad = (uint32_t*)(wcat + 3 * WSZ + 64 * DM);

    dim3 bW(32, 8);

    // --- prep ---
    zero_misc<<<GSZ / 256, 256>>>(gq, gk, cs, pad);
    wconv4<<<dim3(DM / 32, DM / 32, 4), bW>>>(Wq, Wk, Wv, Wt, wcat, wt);
    sgemm_small<<<dim3(1, DM / 64), 256>>>(Wq, Wqa, zv, s2);
    wconv_t<<<dim3(HG / 32, DM / 32), bW>>>(s2, ws1, HG);
    bias_comb<<<1, 256>>>(bq, Wqa, bqa, b1);
    wconv_t<<<dim3(HG / 32, DM / 32), bW>>>(Wka, ws2, HG);
    tofp16<<<(MROWS * DM / 4) / 256, 256>>>((const float4*)hs, (__half2*)ah);

    // --- fused q,k,v,s1 projection ---
    gemm_qkvs<<<dim3(25, MROWS / 128), 256, SMEM_BIG>>>(
        ah, wcat, bq, bk, bv, b1, mask, qh, kh, vh, s1);

    // --- q-attention: colsum, gsum(exp), (max,min) table ---
    sum_cols<<<dim3(BATCH, SEQ / 256), 256>>>(s1, cs);
    gsum_h<<<dim3(BATCH * NH, SEQ / 256), 256>>>(qh, s1, gq);
    gminmax<<<(GSZ / 4) / 256, 256>>>(gq, cs, gmm1);

    // --- ksc (fused qk from kh+gmm1) -> gk -> (max,min) table ---
    gemm_n64_f<<<MROWS / 128, 256, SMEM_N64F>>>(kh, gmm1, ws2, bka, mask, s2);
    gsum_h<<<dim3(BATCH * NH, SEQ / 256), 256>>>(kh, s2, gk);
    gminmax<<<(GSZ / 4) / 256, 256>>>(gk, nullptr, gmm2);

    // --- out = (fused u from vh+gmm2) @ Wt + bt + qh ---
    gemm_hmma_f<<<dim3(DM / 128, MROWS / 128), 256, SMEM_BIGF>>>(
        vh, gmm2, wt, bt, qh, out);
}